// round 1
// baseline (speedup 1.0000x reference)
#include <cuda_runtime.h>

#define Nn 100000
#define Ee 800000
#define Gg 2048
#define Fin 74
#define Hh 256
#define M1d 1024
#define M2d 512

// ---------------- scratch (device globals; no runtime allocation) ----------
__device__ int   g_row_ptr[Nn + 1];
__device__ int   g_cursor[Nn];
__device__ int   g_col[Ee];
__device__ float g_outnorm[Nn];
__device__ float g_innorm[Nn];
__device__ float g_x [Nn * Hh];
__device__ float g_xs[Nn * Hh];
__device__ float g_m [Nn * Hh];
__device__ float g_gsum[Gg * Hh];
__device__ float g_gcnt[Gg];
__device__ float g_z1[Gg * M1d];
__device__ float g_z2[Gg * M2d];
__device__ int   g_part[256];

// ---------------- helpers ----------------
__global__ void k_zero_int(int* p, int n) {
    for (int i = blockIdx.x * blockDim.x + threadIdx.x; i < n; i += gridDim.x * blockDim.x)
        p[i] = 0;
}
__global__ void k_zero_f(float* p, int n) {
    for (int i = blockIdx.x * blockDim.x + threadIdx.x; i < n; i += gridDim.x * blockDim.x)
        p[i] = 0.f;
}

// degrees: row_ptr[dst+1] = in-deg counts ; cursor[src] = out-deg counts
__global__ void k_hist(const int* __restrict__ src, const int* __restrict__ dst) {
    for (int e = blockIdx.x * blockDim.x + threadIdx.x; e < Ee; e += gridDim.x * blockDim.x) {
        atomicAdd(&g_row_ptr[dst[e] + 1], 1);
        atomicAdd(&g_cursor[src[e]], 1);
    }
}

// norms from degree counts; reset cursor for the CSR fill pass
__global__ void k_norms() {
    for (int i = blockIdx.x * blockDim.x + threadIdx.x; i < Nn; i += gridDim.x * blockDim.x) {
        float od = (float)g_cursor[i];
        float id = (float)g_row_ptr[i + 1];
        g_outnorm[i] = rsqrtf(fmaxf(od, 1.f));
        g_innorm[i]  = rsqrtf(fmaxf(id, 1.f));
        g_cursor[i]  = 0;
    }
}

// inclusive scan over row_ptr[0..Nn] (3-pass)
__global__ void k_scan1(int* data, int n, int* part) {
    __shared__ int sh[1024];
    int g = blockIdx.x * 1024 + threadIdx.x;
    int v = (g < n) ? data[g] : 0;
    sh[threadIdx.x] = v;
    __syncthreads();
    for (int off = 1; off < 1024; off <<= 1) {
        int t = (threadIdx.x >= off) ? sh[threadIdx.x - off] : 0;
        __syncthreads();
        sh[threadIdx.x] += t;
        __syncthreads();
    }
    if (g < n) data[g] = sh[threadIdx.x];
    if (threadIdx.x == 1023) part[blockIdx.x] = sh[1023];
}
__global__ void k_scan2(int* part, int nb) {
    if (threadIdx.x == 0 && blockIdx.x == 0) {
        int acc = 0;
        for (int i = 0; i < nb; i++) { acc += part[i]; part[i] = acc; }
    }
}
__global__ void k_scan3(int* data, int n, const int* part) {
    int b = blockIdx.x;
    if (b == 0) return;
    int g = b * 1024 + threadIdx.x;
    if (g < n) data[g] += part[b - 1];
}

// CSR fill (order within a row nondeterministic; fp32 sum reorder only ~ulp)
__global__ void k_fill(const int* __restrict__ src, const int* __restrict__ dst) {
    for (int e = blockIdx.x * blockDim.x + threadIdx.x; e < Ee; e += gridDim.x * blockDim.x) {
        int r = dst[e];
        int p = g_row_ptr[r] + atomicAdd(&g_cursor[r], 1);
        g_col[p] = src[e];
    }
}

// xs = (relu?)x * out_norm[row]
__global__ void k_scale(const float* __restrict__ x, float* __restrict__ xs, int n, int F, int relu_in) {
    for (int i = blockIdx.x * blockDim.x + threadIdx.x; i < n; i += gridDim.x * blockDim.x) {
        int row = i / F;
        float v = x[i];
        if (relu_in) v = fmaxf(v, 0.f);
        xs[i] = v * g_outnorm[row];
    }
}

// m[row,f] = in_norm[row] * sum_{e in row} xs[col[e], f]
__global__ void k_spmm(const float* __restrict__ xs, float* __restrict__ m, int F) {
    int row = blockIdx.x;
    int f = threadIdx.x;
    if (f >= F) return;
    int s = g_row_ptr[row], e = g_row_ptr[row + 1];
    float acc = 0.f;
    for (int i = s; i < e; i++)
        acc += xs[g_col[i] * F + f];
    m[row * F + f] = acc * g_innorm[row];
}

// C[M,Nc] = A[M,K] @ B[K,Nc] + bias ; act: 0 none, 1 relu, 2 leaky(0.01)
__global__ void k_gemm(const float* __restrict__ A, const float* __restrict__ B,
                       const float* __restrict__ bias, float* __restrict__ C,
                       int M, int Nc, int K, int act) {
    __shared__ float As[16][65];
    __shared__ float Bs[16][64];
    int tid = threadIdx.x;
    int tx = tid & 15, ty = tid >> 4;
    int row0 = blockIdx.y * 64, col0 = blockIdx.x * 64;
    float acc[4][4] = {};

    for (int k0 = 0; k0 < K; k0 += 16) {
        int ar = tid >> 2, ac = (tid & 3) * 4;
        int arow = row0 + ar;
#pragma unroll
        for (int j = 0; j < 4; j++) {
            int kk = k0 + ac + j;
            As[ac + j][ar] = (arow < M && kk < K) ? A[arow * K + kk] : 0.f;
        }
        int br = tid >> 4, bc = (tid & 15) * 4;
        int kb = k0 + br;
#pragma unroll
        for (int j = 0; j < 4; j++)
            Bs[br][bc + j] = (kb < K) ? B[kb * Nc + col0 + bc + j] : 0.f;
        __syncthreads();
#pragma unroll
        for (int kk = 0; kk < 16; kk++) {
            float a[4], b[4];
#pragma unroll
            for (int i = 0; i < 4; i++) a[i] = As[kk][ty * 4 + i];
#pragma unroll
            for (int j = 0; j < 4; j++) b[j] = Bs[kk][tx * 4 + j];
#pragma unroll
            for (int i = 0; i < 4; i++)
#pragma unroll
                for (int j = 0; j < 4; j++) acc[i][j] += a[i] * b[j];
        }
        __syncthreads();
    }
#pragma unroll
    for (int i = 0; i < 4; i++) {
        int row = row0 + ty * 4 + i;
        if (row >= M) continue;
#pragma unroll
        for (int j = 0; j < 4; j++) {
            int col = col0 + tx * 4 + j;
            float v = acc[i][j] + bias[col];
            if (act == 1) v = fmaxf(v, 0.f);
            else if (act == 2) v = v > 0.f ? v : 0.01f * v;
            C[row * Nc + col] = v;
        }
    }
}

// graph mean pooling
__global__ void k_pool_sum(const float* __restrict__ x, const int* __restrict__ gid) {
    for (int i = blockIdx.x * blockDim.x + threadIdx.x; i < Nn * Hh; i += gridDim.x * blockDim.x) {
        int node = i >> 8;
        int f = i & 255;
        atomicAdd(&g_gsum[gid[node] * Hh + f], x[i]);
    }
}
__global__ void k_pool_cnt(const int* __restrict__ gid) {
    for (int i = blockIdx.x * blockDim.x + threadIdx.x; i < Nn; i += gridDim.x * blockDim.x)
        atomicAdd(&g_gcnt[gid[i]], 1.f);
}
__global__ void k_pool_div() {
    for (int i = blockIdx.x * blockDim.x + threadIdx.x; i < Gg * Hh; i += gridDim.x * blockDim.x)
        g_gsum[i] /= fmaxf(g_gcnt[i >> 8], 1.f);
}

// out[g] = z2[g,:] . W3 + b3
__global__ void k_final(const float* __restrict__ z2, const float* __restrict__ W3,
                        const float* __restrict__ b3, float* __restrict__ out) {
    int gph = blockIdx.x;
    float acc = 0.f;
    for (int i = threadIdx.x; i < M2d; i += 128)
        acc += z2[gph * M2d + i] * W3[i];
#pragma unroll
    for (int off = 16; off; off >>= 1)
        acc += __shfl_down_sync(0xffffffffu, acc, off);
    __shared__ float sh[4];
    if ((threadIdx.x & 31) == 0) sh[threadIdx.x >> 5] = acc;
    __syncthreads();
    if (threadIdx.x == 0) out[gph] = sh[0] + sh[1] + sh[2] + sh[3] + b3[0];
}

// ---------------- host ----------------
extern "C" void kernel_launch(void* const* d_in, const int* in_sizes, int n_in,
                              void* d_out, int out_size) {
    const float* h    = (const float*)d_in[0];
    const int*   src  = (const int*)d_in[1];
    const int*   dst  = (const int*)d_in[2];
    const int*   gid  = (const int*)d_in[3];
    const float* W_in = (const float*)d_in[4];
    const float* b_in = (const float*)d_in[5];
    const float* Wg   = (const float*)d_in[6];
    const float* bg   = (const float*)d_in[7];
    const float* W1   = (const float*)d_in[8];
    const float* b1   = (const float*)d_in[9];
    const float* W2   = (const float*)d_in[10];
    const float* b2   = (const float*)d_in[11];
    const float* W3   = (const float*)d_in[12];
    const float* b3   = (const float*)d_in[13];
    float* out = (float*)d_out;

    float *p_x, *p_xs, *p_m, *p_gsum, *p_gcnt, *p_z1, *p_z2;
    int *p_rp, *p_cur, *p_part;
    cudaGetSymbolAddress((void**)&p_x,    g_x);
    cudaGetSymbolAddress((void**)&p_xs,   g_xs);
    cudaGetSymbolAddress((void**)&p_m,    g_m);
    cudaGetSymbolAddress((void**)&p_gsum, g_gsum);
    cudaGetSymbolAddress((void**)&p_gcnt, g_gcnt);
    cudaGetSymbolAddress((void**)&p_z1,   g_z1);
    cudaGetSymbolAddress((void**)&p_z2,   g_z2);
    cudaGetSymbolAddress((void**)&p_rp,   g_row_ptr);
    cudaGetSymbolAddress((void**)&p_cur,  g_cursor);
    cudaGetSymbolAddress((void**)&p_part, g_part);

    const int TPB = 256, GB = 512;

    // ---- CSR + norms ----
    k_zero_int<<<GB, TPB>>>(p_rp, Nn + 1);
    k_zero_int<<<GB, TPB>>>(p_cur, Nn);
    k_hist<<<GB, TPB>>>(src, dst);
    k_norms<<<GB, TPB>>>();
    int nscan = Nn + 1;
    int nb = (nscan + 1023) / 1024;            // 98 blocks
    k_scan1<<<nb, 1024>>>(p_rp, nscan, p_part);
    k_scan2<<<1, 32>>>(p_part, nb);
    k_scan3<<<nb, 1024>>>(p_rp, nscan, p_part);
    k_fill<<<GB, TPB>>>(src, dst);

    // ---- input conv: spmm(F=74) then GEMM 74->256 ----
    k_scale<<<GB, TPB>>>(h, p_xs, Nn * Fin, Fin, 0);
    k_spmm<<<Nn, 96>>>(p_xs, p_m, Fin);
    {
        dim3 grid(Hh / 64, (Nn + 63) / 64);
        k_gemm<<<grid, 256>>>(p_m, W_in, b_in, p_x, Nn, Hh, Fin, 0);
    }

    // ---- 5 GCR blocks = 10 H x H convs ----
    for (int l = 0; l < 10; l++) {
        int relu_in  = (l & 1);      // second conv of each pair consumes relu(y)
        int relu_out = (l & 1);      // second conv's output gets relu (block output)
        k_scale<<<GB, TPB>>>(p_x, p_xs, Nn * Hh, Hh, relu_in);
        k_spmm<<<Nn, Hh>>>(p_xs, p_m, Hh);
        dim3 grid(Hh / 64, (Nn + 63) / 64);
        k_gemm<<<grid, 256>>>(p_m, Wg + (size_t)l * Hh * Hh, bg + (size_t)l * Hh,
                              p_x, Nn, Hh, Hh, relu_out ? 1 : 0);
    }

    // ---- graph mean pooling ----
    k_zero_f<<<GB, TPB>>>(p_gsum, Gg * Hh);
    k_zero_f<<<8, TPB>>>(p_gcnt, Gg);
    k_pool_sum<<<GB, TPB>>>(p_x, gid);
    k_pool_cnt<<<GB, TPB>>>(gid);
    k_pool_div<<<GB, TPB>>>();

    // ---- MLP head ----
    {
        dim3 grid(M1d / 64, Gg / 64);
        k_gemm<<<grid, 256>>>(p_gsum, W1, b1, p_z1, Gg, M1d, Hh, 2);
    }
    {
        dim3 grid(M2d / 64, Gg / 64);
        k_gemm<<<grid, 256>>>(p_z1, W2, b2, p_z2, Gg, M2d, M1d, 2);
    }
    k_final<<<Gg, 128>>>(p_z2, W3, b3, out);
}

// round 4
// speedup vs baseline: 1.9105x; 1.9105x over previous
#include <cuda_runtime.h>
#include <cuda_bf16.h>
#include <cstdint>

using std::uint32_t;
using std::uint64_t;

#define Nn 100000
#define Ee 800000
#define Gg 2048
#define Fin 74
#define Hh 256
#define M1d 1024
#define M2d 512

// ---------------- scratch (device globals; no runtime allocation) ----------
__device__ int   g_row_ptr[Nn + 1];
__device__ int   g_cursor[Nn];
__device__ int   g_col[Ee];
__device__ float g_outnorm[Nn];
__device__ float g_innorm[Nn];
__device__ float g_x [Nn * Hh];
__device__ float g_xs[Nn * Hh];
__device__ float g_m [Nn * Hh];
__device__ float g_gsum[Gg * Hh];
__device__ float g_z1[Gg * M1d];
__device__ float g_z2[Gg * M2d];
__device__ int   g_part[256];
__device__ int   g_start[Gg + 1];

// pre-transposed bf16 split weights: layout [N, Kpad], K contiguous
__device__ unsigned short g_WTin_hi[256 * 128],   g_WTin_lo[256 * 128];
__device__ unsigned short g_WTg_hi [10 * 256 * 256], g_WTg_lo [10 * 256 * 256];
__device__ unsigned short g_WT1_hi [1024 * 256],  g_WT1_lo [1024 * 256];
__device__ unsigned short g_WT2_hi [512 * 1024],  g_WT2_lo [512 * 1024];

// ---------------- helpers ----------------
__device__ __forceinline__ uint32_t smem_u32(const void* p) {
    uint32_t a;
    asm("{ .reg .u64 t; cvta.to.shared.u64 t, %1; cvt.u32.u64 %0, t; }" : "=r"(a) : "l"(p));
    return a;
}
__device__ __forceinline__ void ldsm4(uint32_t& r0, uint32_t& r1, uint32_t& r2, uint32_t& r3, uint32_t a) {
    asm volatile("ldmatrix.sync.aligned.m8n8.x4.shared.b16 {%0,%1,%2,%3}, [%4];"
        : "=r"(r0), "=r"(r1), "=r"(r2), "=r"(r3) : "r"(a));
}
__device__ __forceinline__ void mma16816(float* c, const uint32_t* a, const uint32_t* b) {
    asm volatile("mma.sync.aligned.m16n8k16.row.col.f32.bf16.bf16.f32 "
        "{%0,%1,%2,%3}, {%4,%5,%6,%7}, {%8,%9}, {%0,%1,%2,%3};"
        : "+f"(c[0]), "+f"(c[1]), "+f"(c[2]), "+f"(c[3])
        : "r"(a[0]), "r"(a[1]), "r"(a[2]), "r"(a[3]), "r"(b[0]), "r"(b[1]));
}

// ---------------- small kernels ----------------
__global__ void k_zero_int(int* p, int n) {
    for (int i = blockIdx.x * blockDim.x + threadIdx.x; i < n; i += gridDim.x * blockDim.x) p[i] = 0;
}
__global__ void k_hist(const int* __restrict__ src, const int* __restrict__ dst) {
    for (int e = blockIdx.x * blockDim.x + threadIdx.x; e < Ee; e += gridDim.x * blockDim.x) {
        atomicAdd(&g_row_ptr[dst[e] + 1], 1);
        atomicAdd(&g_cursor[src[e]], 1);
    }
}
__global__ void k_norms() {
    for (int i = blockIdx.x * blockDim.x + threadIdx.x; i < Nn; i += gridDim.x * blockDim.x) {
        g_outnorm[i] = rsqrtf(fmaxf((float)g_cursor[i], 1.f));
        g_innorm[i]  = rsqrtf(fmaxf((float)g_row_ptr[i + 1], 1.f));
        g_cursor[i]  = 0;
    }
}
__global__ void k_scan1(int* data, int n, int* part) {
    __shared__ int sh[1024];
    int g = blockIdx.x * 1024 + threadIdx.x;
    int v = (g < n) ? data[g] : 0;
    sh[threadIdx.x] = v;
    __syncthreads();
    for (int off = 1; off < 1024; off <<= 1) {
        int t = (threadIdx.x >= off) ? sh[threadIdx.x - off] : 0;
        __syncthreads();
        sh[threadIdx.x] += t;
        __syncthreads();
    }
    if (g < n) data[g] = sh[threadIdx.x];
    if (threadIdx.x == 1023) part[blockIdx.x] = sh[1023];
}
__global__ void k_scan2(int* part, int nb) {
    if (threadIdx.x == 0 && blockIdx.x == 0) {
        int acc = 0;
        for (int i = 0; i < nb; i++) { acc += part[i]; part[i] = acc; }
    }
}
__global__ void k_scan3(int* data, int n, const int* part) {
    int b = blockIdx.x;
    if (b == 0) return;
    int g = b * 1024 + threadIdx.x;
    if (g < n) data[g] += part[b - 1];
}
__global__ void k_fill(const int* __restrict__ src, const int* __restrict__ dst) {
    for (int e = blockIdx.x * blockDim.x + threadIdx.x; e < Ee; e += gridDim.x * blockDim.x) {
        int r = dst[e];
        int p = g_row_ptr[r] + atomicAdd(&g_cursor[r], 1);
        g_col[p] = src[e];
    }
}
__global__ void k_scale(const float* __restrict__ x, float* __restrict__ xs, int n, int F) {
    for (int i = blockIdx.x * blockDim.x + threadIdx.x; i < n; i += gridDim.x * blockDim.x)
        xs[i] = x[i] * g_outnorm[i / F];
}
__global__ void k_spmm(const float* __restrict__ xs, float* __restrict__ m, int F) {
    int row = blockIdx.x;
    int f = threadIdx.x;
    if (f >= F) return;
    int s = g_row_ptr[row], e = g_row_ptr[row + 1];
    float acc = 0.f;
    for (int i = s; i < e; i++)
        acc += __ldg(&xs[(size_t)g_col[i] * F + f]);
    m[(size_t)row * F + f] = acc * g_innorm[row];
}

// weight transpose + bf16 split: out[n*Kpad + k] = split(W[k*N + n]), pad k>=K with 0
__global__ void k_wt(const float* __restrict__ W, int K, int N, int Kpad,
                     unsigned short* __restrict__ hi, unsigned short* __restrict__ lo) {
    int tot = N * Kpad;
    for (int i = blockIdx.x * blockDim.x + threadIdx.x; i < tot; i += gridDim.x * blockDim.x) {
        int n = i / Kpad, k = i - n * Kpad;
        float v = (k < K) ? W[(size_t)k * N + n] : 0.f;
        __nv_bfloat16 h = __float2bfloat16_rn(v);
        float rem = v - __bfloat162float(h);
        hi[i] = __bfloat16_as_ushort(h);
        lo[i] = __bfloat16_as_ushort(__float2bfloat16_rn(rem));
    }
}

// ---------------- HMMA split-bf16 GEMM (mma.sync, no 103a features) -------
// Tile: BM=128 x BN=128, BK=64, 256 threads = 8 warps (warp tile 64x32).
// A fp32 [M, lda] (Kact valid cols); B pre-split bf16 [N, Kpad] K-contig.
// 3 passes per k-step: AhBh + AhBl + AlBh, fp32 register accumulators.
// mode 0: XS = v*outnorm; 1: XS = relu(v)*outnorm; 2: C = relu(v); 3: C = leaky(v)
#define ST_B 144                 // smem row stride in bytes (64 bf16 + 8 pad)
#define OFF_AH 0
#define OFF_AL (128 * ST_B)      // 18432
#define OFF_BH (2 * 128 * ST_B)  // 36864
#define OFF_BL (3 * 128 * ST_B)  // 55296
#define SMEM_SZ (4 * 128 * ST_B) // 73728

__global__ void __launch_bounds__(256, 1)
k_tgemm(const float* __restrict__ A, int M, int lda, int Kact,
        const unsigned short* __restrict__ Bhi, const unsigned short* __restrict__ Blo,
        int Kpad, const float* __restrict__ bias,
        float* __restrict__ C, int ldc,
        float* __restrict__ XS, int mode) {
    extern __shared__ char smem[];
    uint32_t sb = smem_u32(smem);
    int tid  = threadIdx.x;
    int wid  = tid >> 5, lane = tid & 31;
    int wm   = wid >> 2;            // 0..1  (64-row group)
    int wn   = wid & 3;             // 0..3  (32-col group)
    int m0 = blockIdx.x * 128;
    int n0 = blockIdx.y * 128;

    float acc[4][4][4];
#pragma unroll
    for (int i = 0; i < 4; i++)
#pragma unroll
        for (int j = 0; j < 4; j++)
#pragma unroll
            for (int k = 0; k < 4; k++) acc[i][j][k] = 0.f;

    const int nchunks = Kpad >> 6;
    const bool vecA = ((lda & 3) == 0);

    for (int c = 0; c < nchunks; c++) {
        int k0 = c << 6;
        // ---- A chunk [128 x 64] fp32 -> split bf16 ----
        if (vecA) {
#pragma unroll
            for (int it = 0; it < 8; it++) {
                int idx = it * 256 + tid;       // 2048 float4
                int rl = idx >> 4, c4 = idx & 15;
                int row = m0 + rl;
                float4 v = make_float4(0.f, 0.f, 0.f, 0.f);
                if (row < M) v = *(const float4*)(A + (size_t)row * lda + k0 + c4 * 4);
                float vv[4] = {v.x, v.y, v.z, v.w};
                unsigned short hs[4], ls[4];
#pragma unroll
                for (int j = 0; j < 4; j++) {
                    __nv_bfloat16 hb = __float2bfloat16_rn(vv[j]);
                    hs[j] = __bfloat16_as_ushort(hb);
                    ls[j] = __bfloat16_as_ushort(__float2bfloat16_rn(vv[j] - __bfloat162float(hb)));
                }
                uint32_t off = (uint32_t)(rl * ST_B + c4 * 8);
                *(uint2*)(smem + OFF_AH + off) = make_uint2((uint32_t)hs[0] | ((uint32_t)hs[1] << 16),
                                                            (uint32_t)hs[2] | ((uint32_t)hs[3] << 16));
                *(uint2*)(smem + OFF_AL + off) = make_uint2((uint32_t)ls[0] | ((uint32_t)ls[1] << 16),
                                                            (uint32_t)ls[2] | ((uint32_t)ls[3] << 16));
            }
        } else {
#pragma unroll 1
            for (int it = 0; it < 32; it++) {
                int idx = it * 256 + tid;       // 8192 scalars
                int rl = idx >> 6, kk = idx & 63;
                int row = m0 + rl, kg = k0 + kk;
                float v = (row < M && kg < Kact) ? A[(size_t)row * lda + kg] : 0.f;
                __nv_bfloat16 hb = __float2bfloat16_rn(v);
                uint32_t off = (uint32_t)(rl * ST_B + kk * 2);
                *(unsigned short*)(smem + OFF_AH + off) = __bfloat16_as_ushort(hb);
                *(unsigned short*)(smem + OFF_AL + off) =
                    __bfloat16_as_ushort(__float2bfloat16_rn(v - __bfloat162float(hb)));
            }
        }
        // ---- B chunk [128 x 64] pre-split bf16 ----
#pragma unroll
        for (int it = 0; it < 4; it++) {
            int idx = it * 256 + tid;           // 1024 uint4 per buffer
            int rl = idx >> 3, u = idx & 7;
            size_t gofs = (size_t)(n0 + rl) * Kpad + k0 + u * 8;
            uint32_t off = (uint32_t)(rl * ST_B + u * 16);
            *(uint4*)(smem + OFF_BH + off) = *(const uint4*)(Bhi + gofs);
            *(uint4*)(smem + OFF_BL + off) = *(const uint4*)(Blo + gofs);
        }
        __syncthreads();

        // ---- 4 k16-steps ----
#pragma unroll
        for (int ks = 0; ks < 4; ks++) {
            uint32_t Ah[4][4], Al[4][4], Bh[2][4], Bl[2][4];
            // A frags: m-tiles 0..3 (rows 64*wm + 16*t)
            uint32_t arow = (uint32_t)(64 * wm + (lane & 15));
            uint32_t acol = (uint32_t)(ks * 32 + (lane >> 4) * 16);
#pragma unroll
            for (int t = 0; t < 4; t++) {
                uint32_t ao = sb + (arow + 16 * t) * ST_B + acol;
                ldsm4(Ah[t][0], Ah[t][1], Ah[t][2], Ah[t][3], ao + OFF_AH);
                ldsm4(Al[t][0], Al[t][1], Al[t][2], Al[t][3], ao + OFF_AL);
            }
            // B frags: n-tile pairs p=0 (nt 0,1), p=1 (nt 2,3)
            uint32_t brow = (uint32_t)(32 * wn + (lane >> 4) * 8 + (lane & 7));
            uint32_t bcol = (uint32_t)(ks * 32 + ((lane >> 3) & 1) * 16);
#pragma unroll
            for (int p = 0; p < 2; p++) {
                uint32_t bo = sb + (brow + 16 * p) * ST_B + bcol;
                ldsm4(Bh[p][0], Bh[p][1], Bh[p][2], Bh[p][3], bo + OFF_BH);
                ldsm4(Bl[p][0], Bl[p][1], Bl[p][2], Bl[p][3], bo + OFF_BL);
            }
#pragma unroll
            for (int t = 0; t < 4; t++)
#pragma unroll
                for (int p = 0; p < 2; p++) {
                    mma16816(acc[t][2 * p + 0], Ah[t], &Bh[p][0]);
                    mma16816(acc[t][2 * p + 1], Ah[t], &Bh[p][2]);
                    mma16816(acc[t][2 * p + 0], Ah[t], &Bl[p][0]);
                    mma16816(acc[t][2 * p + 1], Ah[t], &Bl[p][2]);
                    mma16816(acc[t][2 * p + 0], Al[t], &Bh[p][0]);
                    mma16816(acc[t][2 * p + 1], Al[t], &Bh[p][2]);
                }
        }
        __syncthreads();
    }

    // ---- epilogue ----
#pragma unroll
    for (int t = 0; t < 4; t++) {
#pragma unroll
        for (int nt = 0; nt < 4; nt++) {
            int col = n0 + 32 * wn + 8 * nt + 2 * (lane & 3);
            float b0 = bias[col], b1 = bias[col + 1];
#pragma unroll
            for (int half = 0; half < 2; half++) {
                int row = m0 + 64 * wm + 16 * t + (lane >> 2) + 8 * half;
                if (row >= M) continue;
                float v0 = acc[t][nt][2 * half + 0] + b0;
                float v1 = acc[t][nt][2 * half + 1] + b1;
                if (mode == 1 || mode == 2) { v0 = fmaxf(v0, 0.f); v1 = fmaxf(v1, 0.f); }
                else if (mode == 3) { v0 = v0 > 0.f ? v0 : 0.01f * v0; v1 = v1 > 0.f ? v1 : 0.01f * v1; }
                if (mode <= 1) {
                    float on = g_outnorm[row];
                    *(float2*)(XS + (size_t)row * 256 + col) = make_float2(v0 * on, v1 * on);
                } else {
                    *(float2*)(C + (size_t)row * ldc + col) = make_float2(v0, v1);
                }
            }
        }
    }
}

// ---------------- pooling (gid sorted -> segments) ----------------
__global__ void k_gbound(const int* __restrict__ gid) {
    int i = blockIdx.x * blockDim.x + threadIdx.x;
    if (i >= Nn) return;
    if (i == 0) { for (int g = 0; g <= gid[0]; g++) g_start[g] = 0; }
    else if (gid[i] != gid[i - 1]) { for (int g = gid[i - 1] + 1; g <= gid[i]; g++) g_start[g] = i; }
    if (i == Nn - 1) { for (int g = gid[i] + 1; g <= Gg; g++) g_start[g] = Nn; }
}
__global__ void k_pool(const float* __restrict__ x) {
    int g = blockIdx.x, f = threadIdx.x;
    int s = g_start[g], e = g_start[g + 1];
    float acc = 0.f;
    for (int r = s; r < e; r++) acc += x[(size_t)r * Hh + f];
    g_gsum[g * Hh + f] = acc / fmaxf((float)(e - s), 1.f);
}

// out[g] = z2[g,:] . W3 + b3
__global__ void k_final(const float* __restrict__ z2, const float* __restrict__ W3,
                        const float* __restrict__ b3, float* __restrict__ out) {
    int gph = blockIdx.x;
    float acc = 0.f;
    for (int i = threadIdx.x; i < M2d; i += 128)
        acc += z2[gph * M2d + i] * W3[i];
#pragma unroll
    for (int off = 16; off; off >>= 1)
        acc += __shfl_down_sync(0xffffffffu, acc, off);
    __shared__ float sh[4];
    if ((threadIdx.x & 31) == 0) sh[threadIdx.x >> 5] = acc;
    __syncthreads();
    if (threadIdx.x == 0) out[gph] = sh[0] + sh[1] + sh[2] + sh[3] + b3[0];
}

// ---------------- host ----------------
extern "C" void kernel_launch(void* const* d_in, const int* in_sizes, int n_in,
                              void* d_out, int out_size) {
    const float* h    = (const float*)d_in[0];
    const int*   src  = (const int*)d_in[1];
    const int*   dst  = (const int*)d_in[2];
    const int*   gid  = (const int*)d_in[3];
    const float* W_in = (const float*)d_in[4];
    const float* b_in = (const float*)d_in[5];
    const float* Wg   = (const float*)d_in[6];
    const float* bg   = (const float*)d_in[7];
    const float* W1   = (const float*)d_in[8];
    const float* b1   = (const float*)d_in[9];
    const float* W2   = (const float*)d_in[10];
    const float* b2   = (const float*)d_in[11];
    const float* W3   = (const float*)d_in[12];
    const float* b3   = (const float*)d_in[13];
    float* out = (float*)d_out;

    float *p_x, *p_xs, *p_m, *p_gsum, *p_z1, *p_z2;
    int *p_rp, *p_cur, *p_part;
    unsigned short *p_win_h, *p_win_l, *p_wg_h, *p_wg_l, *p_w1_h, *p_w1_l, *p_w2_h, *p_w2_l;
    cudaGetSymbolAddress((void**)&p_x,    g_x);
    cudaGetSymbolAddress((void**)&p_xs,   g_xs);
    cudaGetSymbolAddress((void**)&p_m,    g_m);
    cudaGetSymbolAddress((void**)&p_gsum, g_gsum);
    cudaGetSymbolAddress((void**)&p_z1,   g_z1);
    cudaGetSymbolAddress((void**)&p_z2,   g_z2);
    cudaGetSymbolAddress((void**)&p_rp,   g_row_ptr);
    cudaGetSymbolAddress((void**)&p_cur,  g_cursor);
    cudaGetSymbolAddress((void**)&p_part, g_part);
    cudaGetSymbolAddress((void**)&p_win_h, g_WTin_hi);
    cudaGetSymbolAddress((void**)&p_win_l, g_WTin_lo);
    cudaGetSymbolAddress((void**)&p_wg_h,  g_WTg_hi);
    cudaGetSymbolAddress((void**)&p_wg_l,  g_WTg_lo);
    cudaGetSymbolAddress((void**)&p_w1_h,  g_WT1_hi);
    cudaGetSymbolAddress((void**)&p_w1_l,  g_WT1_lo);
    cudaGetSymbolAddress((void**)&p_w2_h,  g_WT2_hi);
    cudaGetSymbolAddress((void**)&p_w2_l,  g_WT2_lo);

    cudaFuncSetAttribute(k_tgemm, cudaFuncAttributeMaxDynamicSharedMemorySize, SMEM_SZ);

    const int TPB = 256, GB = 512;

    // ---- weight transpose + split (tiny, once per launch) ----
    k_wt<<<128, TPB>>>(W_in, Fin, Hh, 128, p_win_h, p_win_l);
    for (int l = 0; l < 10; l++)
        k_wt<<<256, TPB>>>(Wg + (size_t)l * Hh * Hh, Hh, Hh, Hh,
                           p_wg_h + (size_t)l * Hh * Hh, p_wg_l + (size_t)l * Hh * Hh);
    k_wt<<<1024, TPB>>>(W1, Hh, M1d, Hh, p_w1_h, p_w1_l);
    k_wt<<<2048, TPB>>>(W2, M1d, M2d, M1d, p_w2_h, p_w2_l);

    // ---- CSR + norms ----
    k_zero_int<<<GB, TPB>>>(p_rp, Nn + 1);
    k_zero_int<<<GB, TPB>>>(p_cur, Nn);
    k_hist<<<GB, TPB>>>(src, dst);
    k_norms<<<GB, TPB>>>();
    int nscan = Nn + 1;
    int nb = (nscan + 1023) / 1024;
    k_scan1<<<nb, 1024>>>(p_rp, nscan, p_part);
    k_scan2<<<1, 32>>>(p_part, nb);
    k_scan3<<<nb, 1024>>>(p_rp, nscan, p_part);
    k_fill<<<GB, TPB>>>(src, dst);

    const int MT = (Nn + 127) / 128;   // 782 row tiles

    // ---- input conv: scale -> spmm(74) -> gemm(74->256), epilogue writes xs ----
    k_scale<<<GB, TPB>>>(h, p_xs, Nn * Fin, Fin);
    k_spmm<<<Nn, 96>>>(p_xs, p_m, Fin);
    {
        dim3 grid(MT, Hh / 128);
        k_tgemm<<<grid, 256, SMEM_SZ>>>(p_m, Nn, Fin, Fin, p_win_h, p_win_l, 128,
                                        b_in, nullptr, 256, p_xs, /*mode*/0);
    }

    // ---- 10 H x H graph convs (xs fused into epilogue; layer 9 writes x) ----
    for (int l = 0; l < 10; l++) {
        k_spmm<<<Nn, Hh>>>(p_xs, p_m, Hh);
        dim3 grid(MT, Hh / 128);
        int mode = (l < 9) ? 1 : 2;
        k_tgemm<<<grid, 256, SMEM_SZ>>>(p_m, Nn, Hh, Hh,
                                        p_wg_h + (size_t)l * Hh * Hh, p_wg_l + (size_t)l * Hh * Hh, Hh,
                                        bg + (size_t)l * Hh,
                                        p_x, 256, p_xs, mode);
    }

    // ---- segment mean pooling (gid sorted) ----
    k_gbound<<<(Nn + TPB - 1) / TPB, TPB>>>(gid);
    k_pool<<<Gg, Hh>>>(p_x);

    // ---- MLP head on tensor cores ----
    {
        dim3 grid(Gg / 128, M1d / 128);
        k_tgemm<<<grid, 256, SMEM_SZ>>>(p_gsum, Gg, Hh, Hh, p_w1_h, p_w1_l, Hh,
                                        b1, p_z1, M1d, nullptr, 3);
    }
    {
        dim3 grid(Gg / 128, M2d / 128);
        k_tgemm<<<grid, 256, SMEM_SZ>>>(p_z1, Gg, M1d, M1d, p_w2_h, p_w2_l, M1d,
                                        b2, p_z2, M2d, nullptr, 3);
    }
    k_final<<<Gg, 128>>>(p_z2, W3, b3, out);
}

// round 6
// speedup vs baseline: 2.8845x; 1.5098x over previous
#include <cuda_runtime.h>
#include <cuda_bf16.h>
#include <cstdint>

using std::uint32_t;
using std::uint64_t;

#define Nn 100000
#define Ee 800000
#define Gg 2048
#define Fin 74
#define Hh 256
#define M1d 1024
#define M2d 512

// ---------------- scratch (device globals; no runtime allocation) ----------
__device__ int   g_row_ptr[Nn + 1];
__device__ int   g_cursor[Nn];
__device__ int   g_col[Ee];
__device__ float g_outnorm[Nn];
__device__ float g_innorm[Nn];
__device__ float g_x [Nn * Hh];
__device__ float g_xs[Nn * Hh];
__device__ float g_z2[Gg * M2d];
__device__ int   g_part[256];
__device__ int   g_start[Gg + 1];

// split-bf16 activation buffers (A operands of the GEMMs)
__device__ unsigned short g_mh[Nn * Hh],  g_ml[Nn * Hh];     // spmm output
__device__ unsigned short g_gsh[Gg * Hh], g_gsl[Gg * Hh];    // pooled means
__device__ unsigned short g_z1h[Gg * M1d], g_z1l[Gg * M1d];  // MLP1 output

// pre-transposed bf16 split weights: layout [N, Kpad], K contiguous
__device__ unsigned short g_WTin_hi[256 * 128],   g_WTin_lo[256 * 128];
__device__ unsigned short g_WTg_hi [10 * 256 * 256], g_WTg_lo [10 * 256 * 256];
__device__ unsigned short g_WT1_hi [1024 * 256],  g_WT1_lo [1024 * 256];
__device__ unsigned short g_WT2_hi [512 * 1024],  g_WT2_lo [512 * 1024];

// ---------------- helpers ----------------
__device__ __forceinline__ uint32_t smem_u32(const void* p) {
    uint32_t a;
    asm("{ .reg .u64 t; cvta.to.shared.u64 t, %1; cvt.u32.u64 %0, t; }" : "=r"(a) : "l"(p));
    return a;
}
__device__ __forceinline__ void ldsm4(uint32_t& r0, uint32_t& r1, uint32_t& r2, uint32_t& r3, uint32_t a) {
    asm volatile("ldmatrix.sync.aligned.m8n8.x4.shared.b16 {%0,%1,%2,%3}, [%4];"
        : "=r"(r0), "=r"(r1), "=r"(r2), "=r"(r3) : "r"(a));
}
__device__ __forceinline__ void mma16816(float* c, const uint32_t* a, const uint32_t* b) {
    asm volatile("mma.sync.aligned.m16n8k16.row.col.f32.bf16.bf16.f32 "
        "{%0,%1,%2,%3}, {%4,%5,%6,%7}, {%8,%9}, {%0,%1,%2,%3};"
        : "+f"(c[0]), "+f"(c[1]), "+f"(c[2]), "+f"(c[3])
        : "r"(a[0]), "r"(a[1]), "r"(a[2]), "r"(a[3]), "r"(b[0]), "r"(b[1]));
}
__device__ __forceinline__ void cpa16(uint32_t dst, const void* src) {
    asm volatile("cp.async.cg.shared.global [%0], [%1], 16;" :: "r"(dst), "l"(src));
}
#define CP_COMMIT() asm volatile("cp.async.commit_group;" ::: "memory")
#define CP_WAIT(n)  asm volatile("cp.async.wait_group %0;" :: "n"(n) : "memory")

__device__ __forceinline__ void split_bf16(float v, unsigned short& h, unsigned short& l) {
    __nv_bfloat16 hb = __float2bfloat16_rn(v);
    h = __bfloat16_as_ushort(hb);
    l = __bfloat16_as_ushort(__float2bfloat16_rn(v - __bfloat162float(hb)));
}

// ---------------- small kernels ----------------
__global__ void k_zero_int(int* p, int n) {
    for (int i = blockIdx.x * blockDim.x + threadIdx.x; i < n; i += gridDim.x * blockDim.x) p[i] = 0;
}
__global__ void k_hist(const int* __restrict__ src, const int* __restrict__ dst) {
    for (int e = blockIdx.x * blockDim.x + threadIdx.x; e < Ee; e += gridDim.x * blockDim.x) {
        atomicAdd(&g_row_ptr[dst[e] + 1], 1);
        atomicAdd(&g_cursor[src[e]], 1);
    }
}
__global__ void k_norms() {
    for (int i = blockIdx.x * blockDim.x + threadIdx.x; i < Nn; i += gridDim.x * blockDim.x) {
        g_outnorm[i] = rsqrtf(fmaxf((float)g_cursor[i], 1.f));
        g_innorm[i]  = rsqrtf(fmaxf((float)g_row_ptr[i + 1], 1.f));
        g_cursor[i]  = 0;
    }
}
__global__ void k_scan1(int* data, int n, int* part) {
    __shared__ int sh[1024];
    int g = blockIdx.x * 1024 + threadIdx.x;
    int v = (g < n) ? data[g] : 0;
    sh[threadIdx.x] = v;
    __syncthreads();
    for (int off = 1; off < 1024; off <<= 1) {
        int t = (threadIdx.x >= off) ? sh[threadIdx.x - off] : 0;
        __syncthreads();
        sh[threadIdx.x] += t;
        __syncthreads();
    }
    if (g < n) data[g] = sh[threadIdx.x];
    if (threadIdx.x == 1023) part[blockIdx.x] = sh[1023];
}
__global__ void k_scan2(int* part, int nb) {
    if (threadIdx.x == 0 && blockIdx.x == 0) {
        int acc = 0;
        for (int i = 0; i < nb; i++) { acc += part[i]; part[i] = acc; }
    }
}
__global__ void k_scan3(int* data, int n, const int* part) {
    int b = blockIdx.x;
    if (b == 0) return;
    int g = b * 1024 + threadIdx.x;
    if (g < n) data[g] += part[b - 1];
}
__global__ void k_fill(const int* __restrict__ src, const int* __restrict__ dst) {
    for (int e = blockIdx.x * blockDim.x + threadIdx.x; e < Ee; e += gridDim.x * blockDim.x) {
        int r = dst[e];
        int p = g_row_ptr[r] + atomicAdd(&g_cursor[r], 1);
        g_col[p] = src[e];
    }
}
__global__ void k_scale(const float* __restrict__ x, float* __restrict__ xs, int n, int F) {
    for (int i = blockIdx.x * blockDim.x + threadIdx.x; i < n; i += gridDim.x * blockDim.x)
        xs[i] = x[i] * g_outnorm[i / F];
}

// SpMM F=74: scalar, writes split bf16 into stride-128 arrays (cols 74..127 pre-zeroed)
__global__ void k_spmm74(const float* __restrict__ xs,
                         unsigned short* __restrict__ mh, unsigned short* __restrict__ ml) {
    int row = blockIdx.x, f = threadIdx.x;
    if (f >= Fin) return;
    int s = g_row_ptr[row], e = g_row_ptr[row + 1];
    float acc = 0.f;
    for (int i = s; i < e; i++)
        acc += __ldg(&xs[(size_t)g_col[i] * Fin + f]);
    float v = acc * g_innorm[row];
    unsigned short h, l;
    split_bf16(v, h, l);
    mh[(size_t)row * 128 + f] = h;
    ml[(size_t)row * 128 + f] = l;
}

// SpMM F=256: 128 threads, float2 gather, split-bf16 output stride 256
__global__ void k_spmm256(const float* __restrict__ xs,
                          unsigned short* __restrict__ mh, unsigned short* __restrict__ ml) {
    int row = blockIdx.x, t = threadIdx.x;   // 128
    int s = g_row_ptr[row], e = g_row_ptr[row + 1];
    float ax = 0.f, ay = 0.f;
    for (int i = s; i < e; i++) {
        const float2 v = __ldg((const float2*)(xs + (size_t)g_col[i] * 256 + 2 * t));
        ax += v.x; ay += v.y;
    }
    float inn = g_innorm[row];
    unsigned short h0, l0, h1, l1;
    split_bf16(ax * inn, h0, l0);
    split_bf16(ay * inn, h1, l1);
    *(ushort2*)(mh + (size_t)row * 256 + 2 * t) = make_ushort2(h0, h1);
    *(ushort2*)(ml + (size_t)row * 256 + 2 * t) = make_ushort2(l0, l1);
}

// weight transpose + bf16 split: out[n*Kpad + k] = split(W[k*N + n]), pad k>=K with 0
__global__ void k_wt(const float* __restrict__ W, int K, int N, int Kpad,
                     unsigned short* __restrict__ hi, unsigned short* __restrict__ lo) {
    int tot = N * Kpad;
    for (int i = blockIdx.x * blockDim.x + threadIdx.x; i < tot; i += gridDim.x * blockDim.x) {
        int n = i / Kpad, k = i - n * Kpad;
        float v = (k < K) ? W[(size_t)k * N + n] : 0.f;
        unsigned short h, l;
        split_bf16(v, h, l);
        hi[i] = h; lo[i] = l;
    }
}

// ---------------- HMMA split-bf16 GEMM, cp.async double-buffered -----------
// Tile BM=128 x BN=128, BK=64, 256 threads = 8 warps (warp tile 64x32).
// A pre-split bf16 hi/lo [M, ldk]; B pre-split bf16 [N, ldk].
// 3 passes: AhBh + AhBl + AlBh, fp32 accum.
// mode 0: C = (v+b)*outnorm       1: C = relu(v+b)*outnorm
// mode 2: C = relu(v+b)           3: C = leaky(v+b)
// mode 4: Ch/Cl = split(leaky(v+b))
#define ST_B 144
#define OFF_AH 0
#define OFF_AL (128 * ST_B)
#define OFF_BH (2 * 128 * ST_B)
#define OFF_BL (3 * 128 * ST_B)
#define STG    (4 * 128 * ST_B)      // 73728 per stage
#define SMEM_SZ (2 * STG)            // 147456

__global__ void __launch_bounds__(256, 1)
k_bgemm(const unsigned short* __restrict__ Ah, const unsigned short* __restrict__ Al,
        int M, int ldk,
        const unsigned short* __restrict__ Bhi, const unsigned short* __restrict__ Blo,
        const float* __restrict__ bias,
        float* __restrict__ C, int ldc,
        unsigned short* __restrict__ Ch, unsigned short* __restrict__ Cl,
        int mode) {
    extern __shared__ char smem[];
    uint32_t sb = smem_u32(smem);
    int tid  = threadIdx.x;
    int wid  = tid >> 5, lane = tid & 31;
    int wm   = wid >> 2;            // 0..1
    int wn   = wid & 3;             // 0..3
    int m0 = blockIdx.x * 128;
    int n0 = blockIdx.y * 128;

    float acc[4][4][4];
#pragma unroll
    for (int i = 0; i < 4; i++)
#pragma unroll
        for (int j = 0; j < 4; j++)
#pragma unroll
            for (int k = 0; k < 4; k++) acc[i][j][k] = 0.f;

    const int nch = ldk >> 6;

    // ---- stage loader: 16 cp.async x 16B per thread ----
    auto load_stage = [&](int c, int buf) {
        int k0 = c << 6;
        uint32_t so = sb + buf * STG;
#pragma unroll
        for (int it = 0; it < 4; it++) {
            int idx = it * 256 + tid;          // 1024 16B-chunks per operand
            int rl = idx >> 3, u = idx & 7;
            int arow = m0 + rl; if (arow >= M) arow = M - 1;   // clamp; rows >= M never stored
            size_t ga = (size_t)arow * ldk + k0 + u * 8;
            size_t gb = (size_t)(n0 + rl) * ldk + k0 + u * 8;
            uint32_t d = (uint32_t)(rl * ST_B + u * 16);
            cpa16(so + OFF_AH + d, Ah + ga);
            cpa16(so + OFF_AL + d, Al + ga);
            cpa16(so + OFF_BH + d, Bhi + gb);
            cpa16(so + OFF_BL + d, Blo + gb);
        }
    };

    load_stage(0, 0);
    CP_COMMIT();

    for (int c = 0; c < nch; c++) {
        if (c + 1 < nch) { load_stage(c + 1, (c + 1) & 1); CP_COMMIT(); CP_WAIT(1); }
        else             { CP_WAIT(0); }
        __syncthreads();

        uint32_t so = sb + (c & 1) * STG;
#pragma unroll
        for (int ks = 0; ks < 4; ks++) {
            uint32_t Ahf[4][4], Alf[4][4], Bhf[2][4], Blf[2][4];
            uint32_t arow = (uint32_t)(64 * wm + (lane & 15));
            uint32_t acol = (uint32_t)(ks * 32 + (lane >> 4) * 16);
#pragma unroll
            for (int t = 0; t < 4; t++) {
                uint32_t ao = so + (arow + 16 * t) * ST_B + acol;
                ldsm4(Ahf[t][0], Ahf[t][1], Ahf[t][2], Ahf[t][3], ao + OFF_AH);
                ldsm4(Alf[t][0], Alf[t][1], Alf[t][2], Alf[t][3], ao + OFF_AL);
            }
            uint32_t brow = (uint32_t)(32 * wn + (lane >> 4) * 8 + (lane & 7));
            uint32_t bcol = (uint32_t)(ks * 32 + ((lane >> 3) & 1) * 16);
#pragma unroll
            for (int p = 0; p < 2; p++) {
                uint32_t bo = so + (brow + 16 * p) * ST_B + bcol;
                ldsm4(Bhf[p][0], Bhf[p][1], Bhf[p][2], Bhf[p][3], bo + OFF_BH);
                ldsm4(Blf[p][0], Blf[p][1], Blf[p][2], Blf[p][3], bo + OFF_BL);
            }
#pragma unroll
            for (int t = 0; t < 4; t++)
#pragma unroll
                for (int p = 0; p < 2; p++) {
                    mma16816(acc[t][2 * p + 0], Ahf[t], &Bhf[p][0]);
                    mma16816(acc[t][2 * p + 1], Ahf[t], &Bhf[p][2]);
                    mma16816(acc[t][2 * p + 0], Ahf[t], &Blf[p][0]);
                    mma16816(acc[t][2 * p + 1], Ahf[t], &Blf[p][2]);
                    mma16816(acc[t][2 * p + 0], Alf[t], &Bhf[p][0]);
                    mma16816(acc[t][2 * p + 1], Alf[t], &Bhf[p][2]);
                }
        }
        __syncthreads();
    }

    // ---- epilogue ----
#pragma unroll
    for (int t = 0; t < 4; t++) {
#pragma unroll
        for (int nt = 0; nt < 4; nt++) {
            int col = n0 + 32 * wn + 8 * nt + 2 * (lane & 3);
            float b0 = bias[col], b1 = bias[col + 1];
#pragma unroll
            for (int half = 0; half < 2; half++) {
                int row = m0 + 64 * wm + 16 * t + (lane >> 2) + 8 * half;
                if (row >= M) continue;
                float v0 = acc[t][nt][2 * half + 0] + b0;
                float v1 = acc[t][nt][2 * half + 1] + b1;
                if (mode == 1 || mode == 2) { v0 = fmaxf(v0, 0.f); v1 = fmaxf(v1, 0.f); }
                else if (mode >= 3) { v0 = v0 > 0.f ? v0 : 0.01f * v0; v1 = v1 > 0.f ? v1 : 0.01f * v1; }
                if (mode <= 1) {
                    float on = g_outnorm[row];
                    *(float2*)(C + (size_t)row * ldc + col) = make_float2(v0 * on, v1 * on);
                } else if (mode == 4) {
                    unsigned short h0, l0, h1, l1;
                    split_bf16(v0, h0, l0);
                    split_bf16(v1, h1, l1);
                    *(ushort2*)(Ch + (size_t)row * ldc + col) = make_ushort2(h0, h1);
                    *(ushort2*)(Cl + (size_t)row * ldc + col) = make_ushort2(l0, l1);
                } else {
                    *(float2*)(C + (size_t)row * ldc + col) = make_float2(v0, v1);
                }
            }
        }
    }
}

// ---------------- pooling (gid sorted -> segments) ----------------
__global__ void k_gbound(const int* __restrict__ gid) {
    int i = blockIdx.x * blockDim.x + threadIdx.x;
    if (i >= Nn) return;
    if (i == 0) { for (int g = 0; g <= gid[0]; g++) g_start[g] = 0; }
    else if (gid[i] != gid[i - 1]) { for (int g = gid[i - 1] + 1; g <= gid[i]; g++) g_start[g] = i; }
    if (i == Nn - 1) { for (int g = gid[i] + 1; g <= Gg; g++) g_start[g] = Nn; }
}
__global__ void k_pool(const float* __restrict__ x) {
    int g = blockIdx.x, f = threadIdx.x;   // 256
    int s = g_start[g], e = g_start[g + 1];
    float acc = 0.f;
    for (int r = s; r < e; r++) acc += x[(size_t)r * Hh + f];
    float v = acc / fmaxf((float)(e - s), 1.f);
    unsigned short h, l;
    split_bf16(v, h, l);
    g_gsh[g * Hh + f] = h;
    g_gsl[g * Hh + f] = l;
}

// out[g] = z2[g,:] . W3 + b3
__global__ void k_final(const float* __restrict__ z2, const float* __restrict__ W3,
                        const float* __restrict__ b3, float* __restrict__ out) {
    int gph = blockIdx.x;
    float acc = 0.f;
    for (int i = threadIdx.x; i < M2d; i += 128)
        acc += z2[gph * M2d + i] * W3[i];
#pragma unroll
    for (int off = 16; off; off >>= 1)
        acc += __shfl_down_sync(0xffffffffu, acc, off);
    __shared__ float sh[4];
    if ((threadIdx.x & 31) == 0) sh[threadIdx.x >> 5] = acc;
    __syncthreads();
    if (threadIdx.x == 0) out[gph] = sh[0] + sh[1] + sh[2] + sh[3] + b3[0];
}

// ---------------- host ----------------
extern "C" void kernel_launch(void* const* d_in, const int* in_sizes, int n_in,
                              void* d_out, int out_size) {
    const float* h    = (const float*)d_in[0];
    const int*   src  = (const int*)d_in[1];
    const int*   dst  = (const int*)d_in[2];
    const int*   gid  = (const int*)d_in[3];
    const float* W_in = (const float*)d_in[4];
    const float* b_in = (const float*)d_in[5];
    const float* Wg   = (const float*)d_in[6];
    const float* bg   = (const float*)d_in[7];
    const float* W1   = (const float*)d_in[8];
    const float* b1   = (const float*)d_in[9];
    const float* W2   = (const float*)d_in[10];
    const float* b2   = (const float*)d_in[11];
    const float* W3   = (const float*)d_in[12];
    const float* b3   = (const float*)d_in[13];
    float* out = (float*)d_out;

    float *p_x, *p_xs, *p_z2;
    int *p_rp, *p_cur, *p_part;
    unsigned short *p_mh, *p_ml, *p_gsh, *p_gsl, *p_z1h, *p_z1l;
    unsigned short *p_win_h, *p_win_l, *p_wg_h, *p_wg_l, *p_w1_h, *p_w1_l, *p_w2_h, *p_w2_l;
    cudaGetSymbolAddress((void**)&p_x,    g_x);
    cudaGetSymbolAddress((void**)&p_xs,   g_xs);
    cudaGetSymbolAddress((void**)&p_z2,   g_z2);
    cudaGetSymbolAddress((void**)&p_rp,   g_row_ptr);
    cudaGetSymbolAddress((void**)&p_cur,  g_cursor);
    cudaGetSymbolAddress((void**)&p_part, g_part);
    cudaGetSymbolAddress((void**)&p_mh,   g_mh);
    cudaGetSymbolAddress((void**)&p_ml,   g_ml);
    cudaGetSymbolAddress((void**)&p_gsh,  g_gsh);
    cudaGetSymbolAddress((void**)&p_gsl,  g_gsl);
    cudaGetSymbolAddress((void**)&p_z1h,  g_z1h);
    cudaGetSymbolAddress((void**)&p_z1l,  g_z1l);
    cudaGetSymbolAddress((void**)&p_win_h, g_WTin_hi);
    cudaGetSymbolAddress((void**)&p_win_l, g_WTin_lo);
    cudaGetSymbolAddress((void**)&p_wg_h,  g_WTg_hi);
    cudaGetSymbolAddress((void**)&p_wg_l,  g_WTg_lo);
    cudaGetSymbolAddress((void**)&p_w1_h,  g_WT1_hi);
    cudaGetSymbolAddress((void**)&p_w1_l,  g_WT1_lo);
    cudaGetSymbolAddress((void**)&p_w2_h,  g_WT2_hi);
    cudaGetSymbolAddress((void**)&p_w2_l,  g_WT2_lo);

    cudaFuncSetAttribute(k_bgemm, cudaFuncAttributeMaxDynamicSharedMemorySize, SMEM_SZ);

    const int TPB = 256, GB = 512;

    // ---- weight transpose + split ----
    k_wt<<<128, TPB>>>(W_in, Fin, Hh, 128, p_win_h, p_win_l);
    for (int l = 0; l < 10; l++)
        k_wt<<<256, TPB>>>(Wg + (size_t)l * Hh * Hh, Hh, Hh, Hh,
                           p_wg_h + (size_t)l * Hh * Hh, p_wg_l + (size_t)l * Hh * Hh);
    k_wt<<<1024, TPB>>>(W1, Hh, M1d, Hh, p_w1_h, p_w1_l);
    k_wt<<<2048, TPB>>>(W2, M1d, M2d, M1d, p_w2_h, p_w2_l);

    // ---- CSR + norms ----
    k_zero_int<<<GB, TPB>>>(p_rp, Nn + 1);
    k_zero_int<<<GB, TPB>>>(p_cur, Nn);
    k_hist<<<GB, TPB>>>(src, dst);
    k_norms<<<GB, TPB>>>();
    int nscan = Nn + 1;
    int nb = (nscan + 1023) / 1024;
    k_scan1<<<nb, 1024>>>(p_rp, nscan, p_part);
    k_scan2<<<1, 32>>>(p_part, nb);
    k_scan3<<<nb, 1024>>>(p_rp, nscan, p_part);
    k_fill<<<GB, TPB>>>(src, dst);

    const int MT = (Nn + 127) / 128;   // 782

    // ---- input conv: scale -> spmm74 (split out, stride 128) -> gemm ----
    k_zero_int<<<GB, TPB>>>((int*)p_mh, Nn * 128 / 2);   // zero K-pad cols 74..127
    k_zero_int<<<GB, TPB>>>((int*)p_ml, Nn * 128 / 2);
    k_scale<<<GB, TPB>>>(h, p_xs, Nn * Fin, Fin);
    k_spmm74<<<Nn, 96>>>(p_xs, p_mh, p_ml);
    {
        dim3 grid(MT, Hh / 128);
        k_bgemm<<<grid, 256, SMEM_SZ>>>(p_mh, p_ml, Nn, 128, p_win_h, p_win_l,
                                        b_in, p_xs, 256, nullptr, nullptr, /*mode*/0);
    }

    // ---- 10 H x H graph convs ----
    for (int l = 0; l < 10; l++) {
        k_spmm256<<<Nn, 128>>>(p_xs, p_mh, p_ml);
        dim3 grid(MT, Hh / 128);
        int mode = (l < 9) ? 1 : 2;
        float* outp = (l < 9) ? p_xs : p_x;
        k_bgemm<<<grid, 256, SMEM_SZ>>>(p_mh, p_ml, Nn, 256,
                                        p_wg_h + (size_t)l * Hh * Hh, p_wg_l + (size_t)l * Hh * Hh,
                                        bg + (size_t)l * Hh,
                                        outp, 256, nullptr, nullptr, mode);
    }

    // ---- segment mean pooling -> split bf16 ----
    k_gbound<<<(Nn + TPB - 1) / TPB, TPB>>>(gid);
    k_pool<<<Gg, Hh>>>(p_x);

    // ---- MLP head ----
    {
        dim3 grid(Gg / 128, M1d / 128);
        k_bgemm<<<grid, 256, SMEM_SZ>>>(p_gsh, p_gsl, Gg, 256, p_w1_h, p_w1_l,
                                        b1, nullptr, M1d, p_z1h, p_z1l, /*mode*/4);
    }
    {
        dim3 grid(Gg / 128, M2d / 128);
        k_bgemm<<<grid, 256, SMEM_SZ>>>(p_z1h, p_z1l, Gg, 1024, p_w2_h, p_w2_l,
                                        b2, p_z2, M2d, nullptr, nullptr, /*mode*/3);
    }
    k_final<<<Gg, 128>>>(p_z2, W3, b3, out);
}

// round 8
// speedup vs baseline: 2.9687x; 1.0292x over previous
#include <cuda_runtime.h>
#include <cuda_bf16.h>
#include <cstdint>

using std::uint32_t;
using std::uint64_t;

#define Nn 100000
#define Ee 800000
#define Gg 2048
#define Fin 74
#define Hh 256
#define M1d 1024
#define M2d 512

// ---------------- scratch (device globals; no runtime allocation) ----------
__device__ int   g_row_ptr[Nn + 1];
__device__ int   g_cursor[Nn];
__device__ int   g_col[Ee];
__device__ float g_outnorm[Nn];
__device__ float g_innorm[Nn];
__device__ float g_x [Nn * Hh];       // layer-9 output (row-major, for pooling)
__device__ float g_xs[Nn * Hh];       // chunk-planar activations [4][Nn][64]
__device__ float g_z2[Gg * M2d];
__device__ int   g_part[256];
__device__ int   g_start[Gg + 1];

// split-bf16 activation buffers (A operands of the GEMMs)
__device__ unsigned short g_mh[Nn * Hh],  g_ml[Nn * Hh];
__device__ unsigned short g_gsh[Gg * Hh], g_gsl[Gg * Hh];
__device__ unsigned short g_z1h[Gg * M1d], g_z1l[Gg * M1d];

// pre-transposed bf16 split weights: layout [N, Kpad], K contiguous
__device__ unsigned short g_WTin_hi[256 * 128],   g_WTin_lo[256 * 128];
__device__ unsigned short g_WTg_hi [10 * 256 * 256], g_WTg_lo [10 * 256 * 256];
__device__ unsigned short g_WT1_hi [1024 * 256],  g_WT1_lo [1024 * 256];
__device__ unsigned short g_WT2_hi [512 * 1024],  g_WT2_lo [512 * 1024];

// ---------------- helpers ----------------
__device__ __forceinline__ uint32_t smem_u32(const void* p) {
    uint32_t a;
    asm("{ .reg .u64 t; cvta.to.shared.u64 t, %1; cvt.u32.u64 %0, t; }" : "=r"(a) : "l"(p));
    return a;
}
__device__ __forceinline__ void ldsm4(uint32_t& r0, uint32_t& r1, uint32_t& r2, uint32_t& r3, uint32_t a) {
    asm volatile("ldmatrix.sync.aligned.m8n8.x4.shared.b16 {%0,%1,%2,%3}, [%4];"
        : "=r"(r0), "=r"(r1), "=r"(r2), "=r"(r3) : "r"(a));
}
__device__ __forceinline__ void mma16816(float* c, const uint32_t* a, const uint32_t* b) {
    asm volatile("mma.sync.aligned.m16n8k16.row.col.f32.bf16.bf16.f32 "
        "{%0,%1,%2,%3}, {%4,%5,%6,%7}, {%8,%9}, {%0,%1,%2,%3};"
        : "+f"(c[0]), "+f"(c[1]), "+f"(c[2]), "+f"(c[3])
        : "r"(a[0]), "r"(a[1]), "r"(a[2]), "r"(a[3]), "r"(b[0]), "r"(b[1]));
}
__device__ __forceinline__ void cpa16(uint32_t dst, const void* src) {
    asm volatile("cp.async.cg.shared.global [%0], [%1], 16;" :: "r"(dst), "l"(src));
}
#define CP_COMMIT() asm volatile("cp.async.commit_group;" ::: "memory")
#define CP_WAIT(n)  asm volatile("cp.async.wait_group %0;" :: "n"(n) : "memory")

__device__ __forceinline__ void split_bf16(float v, unsigned short& h, unsigned short& l) {
    __nv_bfloat16 hb = __float2bfloat16_rn(v);
    h = __bfloat16_as_ushort(hb);
    l = __bfloat16_as_ushort(__float2bfloat16_rn(v - __bfloat162float(hb)));
}

// ---------------- small kernels ----------------
__global__ void k_zero_int(int* p, int n) {
    for (int i = blockIdx.x * blockDim.x + threadIdx.x; i < n; i += gridDim.x * blockDim.x) p[i] = 0;
}
__global__ void k_hist(const int* __restrict__ src, const int* __restrict__ dst) {
    for (int e = blockIdx.x * blockDim.x + threadIdx.x; e < Ee; e += gridDim.x * blockDim.x) {
        atomicAdd(&g_row_ptr[dst[e] + 1], 1);
        atomicAdd(&g_cursor[src[e]], 1);
    }
}
__global__ void k_norms() {
    for (int i = blockIdx.x * blockDim.x + threadIdx.x; i < Nn; i += gridDim.x * blockDim.x) {
        g_outnorm[i] = rsqrtf(fmaxf((float)g_cursor[i], 1.f));
        g_innorm[i]  = rsqrtf(fmaxf((float)g_row_ptr[i + 1], 1.f));
        g_cursor[i]  = 0;
    }
}
__global__ void k_scan1(int* data, int n, int* part) {
    __shared__ int sh[1024];
    int g = blockIdx.x * 1024 + threadIdx.x;
    int v = (g < n) ? data[g] : 0;
    sh[threadIdx.x] = v;
    __syncthreads();
    for (int off = 1; off < 1024; off <<= 1) {
        int t = (threadIdx.x >= off) ? sh[threadIdx.x - off] : 0;
        __syncthreads();
        sh[threadIdx.x] += t;
        __syncthreads();
    }
    if (g < n) data[g] = sh[threadIdx.x];
    if (threadIdx.x == 1023) part[blockIdx.x] = sh[1023];
}
__global__ void k_scan2(int* part, int nb) {
    if (threadIdx.x == 0 && blockIdx.x == 0) {
        int acc = 0;
        for (int i = 0; i < nb; i++) { acc += part[i]; part[i] = acc; }
    }
}
__global__ void k_scan3(int* data, int n, const int* part) {
    int b = blockIdx.x;
    if (b == 0) return;
    int g = b * 1024 + threadIdx.x;
    if (g < n) data[g] += part[b - 1];
}
__global__ void k_fill(const int* __restrict__ src, const int* __restrict__ dst) {
    for (int e = blockIdx.x * blockDim.x + threadIdx.x; e < Ee; e += gridDim.x * blockDim.x) {
        int r = dst[e];
        int p = g_row_ptr[r] + atomicAdd(&g_cursor[r], 1);
        g_col[p] = src[e];
    }
}
__global__ void k_scale(const float* __restrict__ x, float* __restrict__ xs, int n, int F) {
    for (int i = blockIdx.x * blockDim.x + threadIdx.x; i < n; i += gridDim.x * blockDim.x)
        xs[i] = x[i] * g_outnorm[i / F];
}

// SpMM F=74 (input conv): scalar gather from xs [Nn,74] row-major
__global__ void k_spmm74(const float* __restrict__ xs,
                         unsigned short* __restrict__ mh, unsigned short* __restrict__ ml) {
    int row = blockIdx.x, f = threadIdx.x;
    if (f >= Fin) return;
    int s = g_row_ptr[row], e = g_row_ptr[row + 1];
    float acc = 0.f;
    for (int i = s; i < e; i++)
        acc += __ldg(&xs[(size_t)g_col[i] * Fin + f]);
    float v = acc * g_innorm[row];
    unsigned short h, l;
    split_bf16(v, h, l);
    mh[(size_t)row * 128 + f] = h;
    ml[(size_t)row * 128 + f] = l;
}

// SpMM over one 64-feature chunk plane (L2-resident 25.6 MB working set).
// One warp per row; lanes cover 64 floats as float2.
__global__ void __launch_bounds__(256)
k_spmmc(const float* __restrict__ xsc, unsigned short* __restrict__ mh,
        unsigned short* __restrict__ ml, int cofs) {
    int row  = blockIdx.x * 8 + (threadIdx.x >> 5);
    int lane = threadIdx.x & 31;
    if (row >= Nn) return;
    int s = g_row_ptr[row], e = g_row_ptr[row + 1];
    float ax = 0.f, ay = 0.f;
    for (int i = s; i < e; i++) {
        int cidx = g_col[i];  // uniform across warp -> broadcast
        const float2 v = __ldg((const float2*)(xsc + (size_t)cidx * 64 + 2 * lane));
        ax += v.x; ay += v.y;
    }
    float inn = g_innorm[row];
    unsigned short h0, l0, h1, l1;
    split_bf16(ax * inn, h0, l0);
    split_bf16(ay * inn, h1, l1);
    size_t o = (size_t)row * 256 + cofs + 2 * lane;
    *(ushort2*)(mh + o) = make_ushort2(h0, h1);
    *(ushort2*)(ml + o) = make_ushort2(l0, l1);
}

// weight transpose + bf16 split (single matrix)
__global__ void k_wt(const float* __restrict__ W, int K, int N, int Kpad,
                     unsigned short* __restrict__ hi, unsigned short* __restrict__ lo) {
    int tot = N * Kpad;
    for (int i = blockIdx.x * blockDim.x + threadIdx.x; i < tot; i += gridDim.x * blockDim.x) {
        int n = i / Kpad, k = i - n * Kpad;
        float v = (k < K) ? W[(size_t)k * N + n] : 0.f;
        unsigned short h, l;
        split_bf16(v, h, l);
        hi[i] = h; lo[i] = l;
    }
}
// all 10 GCR weight matrices in one launch
__global__ void k_wt10(const float* __restrict__ W,
                       unsigned short* __restrict__ hi, unsigned short* __restrict__ lo) {
    int tot = 10 * 256 * 256;
    for (int i = blockIdx.x * blockDim.x + threadIdx.x; i < tot; i += gridDim.x * blockDim.x) {
        int l10 = i >> 16;             // layer
        int r = i & 65535;
        int n = r >> 8, k = r & 255;
        float v = W[(size_t)l10 * 65536 + (size_t)k * 256 + n];
        unsigned short h, l;
        split_bf16(v, h, l);
        hi[i] = h; lo[i] = l;
    }
}

// ---------------- HMMA split-bf16 GEMM, cp.async double-buffered -----------
// Tile BM=128 x BN=128, BK=64, 256 threads = 8 warps (warp tile 64x32).
// mode 0: XSC = (v+b)*outnorm (chunk-planar)   1: XSC = relu(v+b)*outnorm (chunk-planar)
// mode 2: C = relu(v+b)  3: C = leaky(v+b)  4: Ch/Cl = split(leaky(v+b))
#define ST_B 144
#define OFF_AH 0
#define OFF_AL (128 * ST_B)
#define OFF_BH (2 * 128 * ST_B)
#define OFF_BL (3 * 128 * ST_B)
#define STG    (4 * 128 * ST_B)
#define SMEM_SZ (2 * STG)

__global__ void __launch_bounds__(256, 1)
k_bgemm(const unsigned short* __restrict__ Ah, const unsigned short* __restrict__ Al,
        int M, int ldk,
        const unsigned short* __restrict__ Bhi, const unsigned short* __restrict__ Blo,
        const float* __restrict__ bias,
        float* __restrict__ C, int ldc,
        unsigned short* __restrict__ Ch, unsigned short* __restrict__ Cl,
        int mode) {
    extern __shared__ char smem[];
    uint32_t sb = smem_u32(smem);
    int tid  = threadIdx.x;
    int wid  = tid >> 5, lane = tid & 31;
    int wm   = wid >> 2;
    int wn   = wid & 3;
    int m0 = blockIdx.x * 128;
    int n0 = blockIdx.y * 128;

    float acc[4][4][4];
#pragma unroll
    for (int i = 0; i < 4; i++)
#pragma unroll
        for (int j = 0; j < 4; j++)
#pragma unroll
            for (int k = 0; k < 4; k++) acc[i][j][k] = 0.f;

    const int nch = ldk >> 6;

    auto load_stage = [&](int c, int buf) {
        int k0 = c << 6;
        uint32_t so = sb + buf * STG;
#pragma unroll
        for (int it = 0; it < 4; it++) {
            int idx = it * 256 + tid;
            int rl = idx >> 3, u = idx & 7;
            int arow = m0 + rl; if (arow >= M) arow = M - 1;
            size_t ga = (size_t)arow * ldk + k0 + u * 8;
            size_t gb = (size_t)(n0 + rl) * ldk + k0 + u * 8;
            uint32_t d = (uint32_t)(rl * ST_B + u * 16);
            cpa16(so + OFF_AH + d, Ah + ga);
            cpa16(so + OFF_AL + d, Al + ga);
            cpa16(so + OFF_BH + d, Bhi + gb);
            cpa16(so + OFF_BL + d, Blo + gb);
        }
    };

    load_stage(0, 0);
    CP_COMMIT();

    for (int c = 0; c < nch; c++) {
        if (c + 1 < nch) { load_stage(c + 1, (c + 1) & 1); CP_COMMIT(); CP_WAIT(1); }
        else             { CP_WAIT(0); }
        __syncthreads();

        uint32_t so = sb + (c & 1) * STG;
#pragma unroll
        for (int ks = 0; ks < 4; ks++) {
            uint32_t Ahf[4][4], Alf[4][4], Bhf[2][4], Blf[2][4];
            uint32_t arow = (uint32_t)(64 * wm + (lane & 15));
            uint32_t acol = (uint32_t)(ks * 32 + (lane >> 4) * 16);
#pragma unroll
            for (int t = 0; t < 4; t++) {
                uint32_t ao = so + (arow + 16 * t) * ST_B + acol;
                ldsm4(Ahf[t][0], Ahf[t][1], Ahf[t][2], Ahf[t][3], ao + OFF_AH);
                ldsm4(Alf[t][0], Alf[t][1], Alf[t][2], Alf[t][3], ao + OFF_AL);
            }
            uint32_t brow = (uint32_t)(32 * wn + (lane >> 4) * 8 + (lane & 7));
            uint32_t bcol = (uint32_t)(ks * 32 + ((lane >> 3) & 1) * 16);
#pragma unroll
            for (int p = 0; p < 2; p++) {
                uint32_t bo = so + (brow + 16 * p) * ST_B + bcol;
                ldsm4(Bhf[p][0], Bhf[p][1], Bhf[p][2], Bhf[p][3], bo + OFF_BH);
                ldsm4(Blf[p][0], Blf[p][1], Blf[p][2], Blf[p][3], bo + OFF_BL);
            }
#pragma unroll
            for (int t = 0; t < 4; t++)
#pragma unroll
                for (int p = 0; p < 2; p++) {
                    mma16816(acc[t][2 * p + 0], Ahf[t], &Bhf[p][0]);
                    mma16816(acc[t][2 * p + 1], Ahf[t], &Bhf[p][2]);
                    mma16816(acc[t][2 * p + 0], Ahf[t], &Blf[p][0]);
                    mma16816(acc[t][2 * p + 1], Ahf[t], &Blf[p][2]);
                    mma16816(acc[t][2 * p + 0], Alf[t], &Bhf[p][0]);
                    mma16816(acc[t][2 * p + 1], Alf[t], &Bhf[p][2]);
                }
        }
        __syncthreads();
    }

    // ---- epilogue ----
#pragma unroll
    for (int t = 0; t < 4; t++) {
#pragma unroll
        for (int nt = 0; nt < 4; nt++) {
            int col = n0 + 32 * wn + 8 * nt + 2 * (lane & 3);
            float b0 = bias[col], b1 = bias[col + 1];
#pragma unroll
            for (int half = 0; half < 2; half++) {
                int row = m0 + 64 * wm + 16 * t + (lane >> 2) + 8 * half;
                if (row >= M) continue;
                float v0 = acc[t][nt][2 * half + 0] + b0;
                float v1 = acc[t][nt][2 * half + 1] + b1;
                if (mode == 1 || mode == 2) { v0 = fmaxf(v0, 0.f); v1 = fmaxf(v1, 0.f); }
                else if (mode >= 3) { v0 = v0 > 0.f ? v0 : 0.01f * v0; v1 = v1 > 0.f ? v1 : 0.01f * v1; }
                if (mode <= 1) {
                    float on = g_outnorm[row];
                    int ch = col >> 6, cf = col & 63;
                    *(float2*)(C + ((size_t)ch * Nn + row) * 64 + cf) = make_float2(v0 * on, v1 * on);
                } else if (mode == 4) {
                    unsigned short h0, l0, h1, l1;
                    split_bf16(v0, h0, l0);
                    split_bf16(v1, h1, l1);
                    *(ushort2*)(Ch + (size_t)row * ldc + col) = make_ushort2(h0, h1);
                    *(ushort2*)(Cl + (size_t)row * ldc + col) = make_ushort2(l0, l1);
                } else {
                    *(float2*)(C + (size_t)row * ldc + col) = make_float2(v0, v1);
                }
            }
        }
    }
}

// ---------------- pooling (gid sorted -> segments) ----------------
__global__ void k_gbound(const int* __restrict__ gid) {
    int i = blockIdx.x * blockDim.x + threadIdx.x;
    if (i >= Nn) return;
    if (i == 0) { for (int g = 0; g <= gid[0]; g++) g_start[g] = 0; }
    else if (gid[i] != gid[i - 1]) { for (int g = gid[i - 1] + 1; g <= gid[i]; g++) g_start[g] = i; }
    if (i == Nn - 1) { for (int g = gid[i] + 1; g <= Gg; g++) g_start[g] = Nn; }
}
__global__ void k_pool(const float* __restrict__ x) {
    int g = blockIdx.x, f = threadIdx.x;
    int s = g_start[g], e = g_start[g + 1];
    float acc = 0.f;
    for (int r = s; r < e; r++) acc += x[(size_t)r * Hh + f];
    float v = acc / fmaxf((float)(e - s), 1.f);
    unsigned short h, l;
    split_bf16(v, h, l);
    g_gsh[g * Hh + f] = h;
    g_gsl[g * Hh + f] = l;
}

__global__ void k_final(const float* __restrict__ z2, const float* __restrict__ W3,
                        const float* __restrict__ b3, float* __restrict__ out) {
    int gph = blockIdx.x;
    float acc = 0.f;
    for (int i = threadIdx.x; i < M2d; i += 128)
        acc += z2[gph * M2d + i] * W3[i];
#pragma unroll
    for (int off = 16; off; off >>= 1)
        acc += __shfl_down_sync(0xffffffffu, acc, off);
    __shared__ float sh[4];
    if ((threadIdx.x & 31) == 0) sh[threadIdx.x >> 5] = acc;
    __syncthreads();
    if (threadIdx.x == 0) out[gph] = sh[0] + sh[1] + sh[2] + sh[3] + b3[0];
}

// ---------------- host ----------------
extern "C" void kernel_launch(void* const* d_in, const int* in_sizes, int n_in,
                              void* d_out, int out_size) {
    const float* h    = (const float*)d_in[0];
    const int*   src  = (const int*)d_in[1];
    const int*   dst  = (const int*)d_in[2];
    const int*   gid  = (const int*)d_in[3];
    const float* W_in = (const float*)d_in[4];
    const float* b_in = (const float*)d_in[5];
    const float* Wg   = (const float*)d_in[6];
    const float* bg   = (const float*)d_in[7];
    const float* W1   = (const float*)d_in[8];
    const float* b1   = (const float*)d_in[9];
    const float* W2   = (const float*)d_in[10];
    const float* b2   = (const float*)d_in[11];
    const float* W3   = (const float*)d_in[12];
    const float* b3   = (const float*)d_in[13];
    float* out = (float*)d_out;

    float *p_x, *p_xs, *p_z2;
    int *p_rp, *p_cur, *p_part;
    unsigned short *p_mh, *p_ml, *p_gsh, *p_gsl, *p_z1h, *p_z1l;
    unsigned short *p_win_h, *p_win_l, *p_wg_h, *p_wg_l, *p_w1_h, *p_w1_l, *p_w2_h, *p_w2_l;
    cudaGetSymbolAddress((void**)&p_x,    g_x);
    cudaGetSymbolAddress((void**)&p_xs,   g_xs);
    cudaGetSymbolAddress((void**)&p_z2,   g_z2);
    cudaGetSymbolAddress((void**)&p_rp,   g_row_ptr);
    cudaGetSymbolAddress((void**)&p_cur,  g_cursor);
    cudaGetSymbolAddress((void**)&p_part, g_part);
    cudaGetSymbolAddress((void**)&p_mh,   g_mh);
    cudaGetSymbolAddress((void**)&p_ml,   g_ml);
    cudaGetSymbolAddress((void**)&p_gsh,  g_gsh);
    cudaGetSymbolAddress((void**)&p_gsl,  g_gsl);
    cudaGetSymbolAddress((void**)&p_z1h,  g_z1h);
    cudaGetSymbolAddress((void**)&p_z1l,  g_z1l);
    cudaGetSymbolAddress((void**)&p_win_h, g_WTin_hi);
    cudaGetSymbolAddress((void**)&p_win_l, g_WTin_lo);
    cudaGetSymbolAddress((void**)&p_wg_h,  g_WTg_hi);
    cudaGetSymbolAddress((void**)&p_wg_l,  g_WTg_lo);
    cudaGetSymbolAddress((void**)&p_w1_h,  g_WT1_hi);
    cudaGetSymbolAddress((void**)&p_w1_l,  g_WT1_lo);
    cudaGetSymbolAddress((void**)&p_w2_h,  g_WT2_hi);
    cudaGetSymbolAddress((void**)&p_w2_l,  g_WT2_lo);

    cudaFuncSetAttribute(k_bgemm, cudaFuncAttributeMaxDynamicSharedMemorySize, SMEM_SZ);

    const int TPB = 256, GB = 512;

    // ---- weight transpose + split ----
    k_wt<<<128, TPB>>>(W_in, Fin, Hh, 128, p_win_h, p_win_l);
    k_wt10<<<640, TPB>>>(Wg, p_wg_h, p_wg_l);
    k_wt<<<1024, TPB>>>(W1, Hh, M1d, Hh, p_w1_h, p_w1_l);
    k_wt<<<2048, TPB>>>(W2, M1d, M2d, M1d, p_w2_h, p_w2_l);

    // ---- CSR + norms ----
    k_zero_int<<<GB, TPB>>>(p_rp, Nn + 1);
    k_zero_int<<<GB, TPB>>>(p_cur, Nn);
    k_hist<<<GB, TPB>>>(src, dst);
    k_norms<<<GB, TPB>>>();
    int nscan = Nn + 1;
    int nb = (nscan + 1023) / 1024;
    k_scan1<<<nb, 1024>>>(p_rp, nscan, p_part);
    k_scan2<<<1, 32>>>(p_part, nb);
    k_scan3<<<nb, 1024>>>(p_rp, nscan, p_part);
    k_fill<<<GB, TPB>>>(src, dst);

    const int MT = (Nn + 127) / 128;     // 782
    const int SPB = (Nn + 7) / 8;        // 12500 blocks (8 rows/block)

    // ---- input conv: scale -> spmm74 -> gemm (epilogue writes chunk-planar xs) ----
    k_zero_int<<<GB, TPB>>>((int*)p_mh, Nn * 128 / 2);
    k_zero_int<<<GB, TPB>>>((int*)p_ml, Nn * 128 / 2);
    k_scale<<<GB, TPB>>>(h, p_xs, Nn * Fin, Fin);
    k_spmm74<<<Nn, 96>>>(p_xs, p_mh, p_ml);
    {
        dim3 grid(MT, Hh / 128);
        k_bgemm<<<grid, 256, SMEM_SZ>>>(p_mh, p_ml, Nn, 128, p_win_h, p_win_l,
                                        b_in, p_xs, 256, nullptr, nullptr, /*mode*/0);
    }

    // ---- 10 H x H graph convs: 4 per-chunk SpMM launches (L2-resident) + gemm ----
    for (int l = 0; l < 10; l++) {
        for (int c = 0; c < 4; c++)
            k_spmmc<<<SPB, 256>>>(p_xs + (size_t)c * Nn * 64, p_mh, p_ml, c * 64);
        dim3 grid(MT, Hh / 128);
        int mode = (l < 9) ? 1 : 2;
        float* outp = (l < 9) ? p_xs : p_x;
        k_bgemm<<<grid, 256, SMEM_SZ>>>(p_mh, p_ml, Nn, 256,
                                        p_wg_h + (size_t)l * Hh * Hh, p_wg_l + (size_t)l * Hh * Hh,
                                        bg + (size_t)l * Hh,
                                        outp, 256, nullptr, nullptr, mode);
    }

    // ---- segment mean pooling -> split bf16 ----
    k_gbound<<<(Nn + TPB - 1) / TPB, TPB>>>(gid);
    k_pool<<<Gg, Hh>>>(p_x);

    // ---- MLP head ----
    {
        dim3 grid(Gg / 128, M1d / 128);
        k_bgemm<<<grid, 256, SMEM_SZ>>>(p_gsh, p_gsl, Gg, 256, p_w1_h, p_w1_l,
                                        b1, nullptr, M1d, p_z1h, p_z1l, /*mode*/4);
    }
    {
        dim3 grid(Gg / 128, M2d / 128);
        k_bgemm<<<grid, 256, SMEM_SZ>>>(p_z1h, p_z1l, Gg, 1024, p_w2_h, p_w2_l,
                                        b2, p_z2, M2d, nullptr, nullptr, /*mode*/3);
    }
    k_final<<<Gg, 128>>>(p_z2, W3, b3, out);
}

// round 9
// speedup vs baseline: 3.1807x; 1.0714x over previous
#include <cuda_runtime.h>
#include <cuda_bf16.h>
#include <cstdint>

using std::uint32_t;
using std::uint64_t;

#define Nn 100000
#define Ee 800000
#define Gg 2048
#define Fin 74
#define Hh 256
#define M1d 1024
#define M2d 512

// ---------------- scratch (device globals; no runtime allocation) ----------
__device__ int   g_row_ptr[Nn + 1];
__device__ int   g_cursor[Nn];
__device__ int   g_col[Ee];
__device__ float g_outnorm[Nn];
__device__ float g_innorm[Nn];
__device__ float g_x [Nn * Hh];       // layer-9 output (row-major, for pooling)
__device__ float g_xs[Nn * Hh];       // row-major activations [Nn][256]
__device__ float g_z2[Gg * M2d];
__device__ int   g_part[256];
__device__ int   g_start[Gg + 1];

// split-bf16 activation buffers (A operands of the GEMMs)
__device__ unsigned short g_mh[Nn * Hh],  g_ml[Nn * Hh];
__device__ unsigned short g_gsh[Gg * Hh], g_gsl[Gg * Hh];
__device__ unsigned short g_z1h[Gg * M1d], g_z1l[Gg * M1d];

// pre-transposed bf16 split weights: layout [N, Kpad], K contiguous
__device__ unsigned short g_WTin_hi[256 * 128],   g_WTin_lo[256 * 128];
__device__ unsigned short g_WTg_hi [10 * 256 * 256], g_WTg_lo [10 * 256 * 256];
__device__ unsigned short g_WT1_hi [1024 * 256],  g_WT1_lo [1024 * 256];
__device__ unsigned short g_WT2_hi [512 * 1024],  g_WT2_lo [512 * 1024];

// ---------------- helpers ----------------
__device__ __forceinline__ uint32_t smem_u32(const void* p) {
    uint32_t a;
    asm("{ .reg .u64 t; cvta.to.shared.u64 t, %1; cvt.u32.u64 %0, t; }" : "=r"(a) : "l"(p));
    return a;
}
__device__ __forceinline__ void ldsm4(uint32_t& r0, uint32_t& r1, uint32_t& r2, uint32_t& r3, uint32_t a) {
    asm volatile("ldmatrix.sync.aligned.m8n8.x4.shared.b16 {%0,%1,%2,%3}, [%4];"
        : "=r"(r0), "=r"(r1), "=r"(r2), "=r"(r3) : "r"(a));
}
__device__ __forceinline__ void mma16816(float* c, const uint32_t* a, const uint32_t* b) {
    asm volatile("mma.sync.aligned.m16n8k16.row.col.f32.bf16.bf16.f32 "
        "{%0,%1,%2,%3}, {%4,%5,%6,%7}, {%8,%9}, {%0,%1,%2,%3};"
        : "+f"(c[0]), "+f"(c[1]), "+f"(c[2]), "+f"(c[3])
        : "r"(a[0]), "r"(a[1]), "r"(a[2]), "r"(a[3]), "r"(b[0]), "r"(b[1]));
}
__device__ __forceinline__ void cpa16(uint32_t dst, const void* src) {
    asm volatile("cp.async.cg.shared.global [%0], [%1], 16;" :: "r"(dst), "l"(src));
}
#define CP_COMMIT() asm volatile("cp.async.commit_group;" ::: "memory")
#define CP_WAIT(n)  asm volatile("cp.async.wait_group %0;" :: "n"(n) : "memory")

__device__ __forceinline__ void split_bf16(float v, unsigned short& h, unsigned short& l) {
    __nv_bfloat16 hb = __float2bfloat16_rn(v);
    h = __bfloat16_as_ushort(hb);
    l = __bfloat16_as_ushort(__float2bfloat16_rn(v - __bfloat162float(hb)));
}

// ---------------- small kernels ----------------
__global__ void k_zero_int(int* p, int n) {
    for (int i = blockIdx.x * blockDim.x + threadIdx.x; i < n; i += gridDim.x * blockDim.x) p[i] = 0;
}
__global__ void k_hist(const int* __restrict__ src, const int* __restrict__ dst) {
    for (int e = blockIdx.x * blockDim.x + threadIdx.x; e < Ee; e += gridDim.x * blockDim.x) {
        atomicAdd(&g_row_ptr[dst[e] + 1], 1);
        atomicAdd(&g_cursor[src[e]], 1);
    }
}
__global__ void k_norms() {
    for (int i = blockIdx.x * blockDim.x + threadIdx.x; i < Nn; i += gridDim.x * blockDim.x) {
        g_outnorm[i] = rsqrtf(fmaxf((float)g_cursor[i], 1.f));
        g_innorm[i]  = rsqrtf(fmaxf((float)g_row_ptr[i + 1], 1.f));
        g_cursor[i]  = 0;
    }
}
__global__ void k_scan1(int* data, int n, int* part) {
    __shared__ int sh[1024];
    int g = blockIdx.x * 1024 + threadIdx.x;
    int v = (g < n) ? data[g] : 0;
    sh[threadIdx.x] = v;
    __syncthreads();
    for (int off = 1; off < 1024; off <<= 1) {
        int t = (threadIdx.x >= off) ? sh[threadIdx.x - off] : 0;
        __syncthreads();
        sh[threadIdx.x] += t;
        __syncthreads();
    }
    if (g < n) data[g] = sh[threadIdx.x];
    if (threadIdx.x == 1023) part[blockIdx.x] = sh[1023];
}
__global__ void k_scan2(int* part, int nb) {
    if (threadIdx.x == 0 && blockIdx.x == 0) {
        int acc = 0;
        for (int i = 0; i < nb; i++) { acc += part[i]; part[i] = acc; }
    }
}
__global__ void k_scan3(int* data, int n, const int* part) {
    int b = blockIdx.x;
    if (b == 0) return;
    int g = b * 1024 + threadIdx.x;
    if (g < n) data[g] += part[b - 1];
}
__global__ void k_fill(const int* __restrict__ src, const int* __restrict__ dst) {
    for (int e = blockIdx.x * blockDim.x + threadIdx.x; e < Ee; e += gridDim.x * blockDim.x) {
        int r = dst[e];
        int p = g_row_ptr[r] + atomicAdd(&g_cursor[r], 1);
        g_col[p] = src[e];
    }
}
__global__ void k_scale(const float* __restrict__ x, float* __restrict__ xs, int n, int F) {
    for (int i = blockIdx.x * blockDim.x + threadIdx.x; i < n; i += gridDim.x * blockDim.x)
        xs[i] = x[i] * g_outnorm[i / F];
}

// SpMM F=74 (input conv): scalar gather from xs [Nn,74] row-major
__global__ void k_spmm74(const float* __restrict__ xs,
                         unsigned short* __restrict__ mh, unsigned short* __restrict__ ml) {
    int row = blockIdx.x, f = threadIdx.x;
    if (f >= Fin) return;
    int s = g_row_ptr[row], e = g_row_ptr[row + 1];
    float acc = 0.f;
    for (int i = s; i < e; i++)
        acc += __ldg(&xs[(size_t)g_col[i] * Fin + f]);
    float v = acc * g_innorm[row];
    unsigned short h, l;
    split_bf16(v, h, l);
    mh[(size_t)row * 128 + f] = h;
    ml[(size_t)row * 128 + f] = l;
}

// SpMM F=256: warp per row, 8 floats/lane (2x LDG.128), edges unrolled x2.
__global__ void __launch_bounds__(256)
k_spmm256(const float* __restrict__ xs,
          unsigned short* __restrict__ mh, unsigned short* __restrict__ ml) {
    int row  = blockIdx.x * 8 + (threadIdx.x >> 5);
    int lane = threadIdx.x & 31;
    if (row >= Nn) return;
    int s = g_row_ptr[row], e = g_row_ptr[row + 1];
    const int* cp = g_col + s;
    int n = e - s;
    float4 A0 = make_float4(0.f, 0.f, 0.f, 0.f);
    float4 A1 = make_float4(0.f, 0.f, 0.f, 0.f);
    int i = 0;
    for (; i + 2 <= n; i += 2) {
        int c0 = __ldg(cp + i), c1 = __ldg(cp + i + 1);
        const float4* p0 = (const float4*)(xs + (size_t)c0 * 256 + lane * 8);
        const float4* p1 = (const float4*)(xs + (size_t)c1 * 256 + lane * 8);
        float4 v00 = __ldg(p0), v01 = __ldg(p0 + 1);
        float4 v10 = __ldg(p1), v11 = __ldg(p1 + 1);
        A0.x += v00.x + v10.x; A0.y += v00.y + v10.y;
        A0.z += v00.z + v10.z; A0.w += v00.w + v10.w;
        A1.x += v01.x + v11.x; A1.y += v01.y + v11.y;
        A1.z += v01.z + v11.z; A1.w += v01.w + v11.w;
    }
    if (i < n) {
        int c0 = __ldg(cp + i);
        const float4* p0 = (const float4*)(xs + (size_t)c0 * 256 + lane * 8);
        float4 v00 = __ldg(p0), v01 = __ldg(p0 + 1);
        A0.x += v00.x; A0.y += v00.y; A0.z += v00.z; A0.w += v00.w;
        A1.x += v01.x; A1.y += v01.y; A1.z += v01.z; A1.w += v01.w;
    }
    float inn = g_innorm[row];
    float v[8] = {A0.x * inn, A0.y * inn, A0.z * inn, A0.w * inn,
                  A1.x * inn, A1.y * inn, A1.z * inn, A1.w * inn};
    unsigned short hs[8], ls[8];
#pragma unroll
    for (int j = 0; j < 8; j++) split_bf16(v[j], hs[j], ls[j]);
    uint4 ph = make_uint4((uint32_t)hs[0] | ((uint32_t)hs[1] << 16),
                          (uint32_t)hs[2] | ((uint32_t)hs[3] << 16),
                          (uint32_t)hs[4] | ((uint32_t)hs[5] << 16),
                          (uint32_t)hs[6] | ((uint32_t)hs[7] << 16));
    uint4 pl = make_uint4((uint32_t)ls[0] | ((uint32_t)ls[1] << 16),
                          (uint32_t)ls[2] | ((uint32_t)ls[3] << 16),
                          (uint32_t)ls[4] | ((uint32_t)ls[5] << 16),
                          (uint32_t)ls[6] | ((uint32_t)ls[7] << 16));
    size_t o = (size_t)row * 256 + lane * 8;
    *(uint4*)(mh + o) = ph;
    *(uint4*)(ml + o) = pl;
}

// weight transpose + bf16 split (single matrix)
__global__ void k_wt(const float* __restrict__ W, int K, int N, int Kpad,
                     unsigned short* __restrict__ hi, unsigned short* __restrict__ lo) {
    int tot = N * Kpad;
    for (int i = blockIdx.x * blockDim.x + threadIdx.x; i < tot; i += gridDim.x * blockDim.x) {
        int n = i / Kpad, k = i - n * Kpad;
        float v = (k < K) ? W[(size_t)k * N + n] : 0.f;
        unsigned short h, l;
        split_bf16(v, h, l);
        hi[i] = h; lo[i] = l;
    }
}
// all 10 GCR weight matrices in one launch
__global__ void k_wt10(const float* __restrict__ W,
                       unsigned short* __restrict__ hi, unsigned short* __restrict__ lo) {
    int tot = 10 * 256 * 256;
    for (int i = blockIdx.x * blockDim.x + threadIdx.x; i < tot; i += gridDim.x * blockDim.x) {
        int l10 = i >> 16;
        int r = i & 65535;
        int n = r >> 8, k = r & 255;
        float v = W[(size_t)l10 * 65536 + (size_t)k * 256 + n];
        unsigned short h, l;
        split_bf16(v, h, l);
        hi[i] = h; lo[i] = l;
    }
}

// ---------------- HMMA split-bf16 GEMM, cp.async double-buffered -----------
// Tile BM=128 x BN=128, BK=64, 256 threads = 8 warps (warp tile 64x32).
// mode 0: C = (v+b)*outnorm   1: C = relu(v+b)*outnorm   (row-major xs)
// mode 2: C = relu(v+b)  3: C = leaky(v+b)  4: Ch/Cl = split(leaky(v+b))
#define ST_B 144
#define OFF_AH 0
#define OFF_AL (128 * ST_B)
#define OFF_BH (2 * 128 * ST_B)
#define OFF_BL (3 * 128 * ST_B)
#define STG    (4 * 128 * ST_B)
#define SMEM_SZ (2 * STG)

__global__ void __launch_bounds__(256, 1)
k_bgemm(const unsigned short* __restrict__ Ah, const unsigned short* __restrict__ Al,
        int M, int ldk,
        const unsigned short* __restrict__ Bhi, const unsigned short* __restrict__ Blo,
        const float* __restrict__ bias,
        float* __restrict__ C, int ldc,
        unsigned short* __restrict__ Ch, unsigned short* __restrict__ Cl,
        int mode) {
    extern __shared__ char smem[];
    uint32_t sb = smem_u32(smem);
    int tid  = threadIdx.x;
    int wid  = tid >> 5, lane = tid & 31;
    int wm   = wid >> 2;
    int wn   = wid & 3;
    int m0 = blockIdx.x * 128;
    int n0 = blockIdx.y * 128;

    float acc[4][4][4];
#pragma unroll
    for (int i = 0; i < 4; i++)
#pragma unroll
        for (int j = 0; j < 4; j++)
#pragma unroll
            for (int k = 0; k < 4; k++) acc[i][j][k] = 0.f;

    const int nch = ldk >> 6;

    auto load_stage = [&](int c, int buf) {
        int k0 = c << 6;
        uint32_t so = sb + buf * STG;
#pragma unroll
        for (int it = 0; it < 4; it++) {
            int idx = it * 256 + tid;
            int rl = idx >> 3, u = idx & 7;
            int arow = m0 + rl; if (arow >= M) arow = M - 1;
            size_t ga = (size_t)arow * ldk + k0 + u * 8;
            size_t gb = (size_t)(n0 + rl) * ldk + k0 + u * 8;
            uint32_t d = (uint32_t)(rl * ST_B + u * 16);
            cpa16(so + OFF_AH + d, Ah + ga);
            cpa16(so + OFF_AL + d, Al + ga);
            cpa16(so + OFF_BH + d, Bhi + gb);
            cpa16(so + OFF_BL + d, Blo + gb);
        }
    };

    load_stage(0, 0);
    CP_COMMIT();

    for (int c = 0; c < nch; c++) {
        if (c + 1 < nch) { load_stage(c + 1, (c + 1) & 1); CP_COMMIT(); CP_WAIT(1); }
        else             { CP_WAIT(0); }
        __syncthreads();

        uint32_t so = sb + (c & 1) * STG;
#pragma unroll
        for (int ks = 0; ks < 4; ks++) {
            uint32_t Ahf[4][4], Alf[4][4], Bhf[2][4], Blf[2][4];
            uint32_t arow = (uint32_t)(64 * wm + (lane & 15));
            uint32_t acol = (uint32_t)(ks * 32 + (lane >> 4) * 16);
#pragma unroll
            for (int t = 0; t < 4; t++) {
                uint32_t ao = so + (arow + 16 * t) * ST_B + acol;
                ldsm4(Ahf[t][0], Ahf[t][1], Ahf[t][2], Ahf[t][3], ao + OFF_AH);
                ldsm4(Alf[t][0], Alf[t][1], Alf[t][2], Alf[t][3], ao + OFF_AL);
            }
            uint32_t brow = (uint32_t)(32 * wn + (lane >> 4) * 8 + (lane & 7));
            uint32_t bcol = (uint32_t)(ks * 32 + ((lane >> 3) & 1) * 16);
#pragma unroll
            for (int p = 0; p < 2; p++) {
                uint32_t bo = so + (brow + 16 * p) * ST_B + bcol;
                ldsm4(Bhf[p][0], Bhf[p][1], Bhf[p][2], Bhf[p][3], bo + OFF_BH);
                ldsm4(Blf[p][0], Blf[p][1], Blf[p][2], Blf[p][3], bo + OFF_BL);
            }
#pragma unroll
            for (int t = 0; t < 4; t++)
#pragma unroll
                for (int p = 0; p < 2; p++) {
                    mma16816(acc[t][2 * p + 0], Ahf[t], &Bhf[p][0]);
                    mma16816(acc[t][2 * p + 1], Ahf[t], &Bhf[p][2]);
                    mma16816(acc[t][2 * p + 0], Ahf[t], &Blf[p][0]);
                    mma16816(acc[t][2 * p + 1], Ahf[t], &Blf[p][2]);
                    mma16816(acc[t][2 * p + 0], Alf[t], &Bhf[p][0]);
                    mma16816(acc[t][2 * p + 1], Alf[t], &Bhf[p][2]);
                }
        }
        __syncthreads();
    }

    // ---- epilogue ----
#pragma unroll
    for (int t = 0; t < 4; t++) {
#pragma unroll
        for (int nt = 0; nt < 4; nt++) {
            int col = n0 + 32 * wn + 8 * nt + 2 * (lane & 3);
            float b0 = bias[col], b1 = bias[col + 1];
#pragma unroll
            for (int half = 0; half < 2; half++) {
                int row = m0 + 64 * wm + 16 * t + (lane >> 2) + 8 * half;
                if (row >= M) continue;
                float v0 = acc[t][nt][2 * half + 0] + b0;
                float v1 = acc[t][nt][2 * half + 1] + b1;
                if (mode == 1 || mode == 2) { v0 = fmaxf(v0, 0.f); v1 = fmaxf(v1, 0.f); }
                else if (mode >= 3) { v0 = v0 > 0.f ? v0 : 0.01f * v0; v1 = v1 > 0.f ? v1 : 0.01f * v1; }
                if (mode <= 1) {
                    float on = g_outnorm[row];
                    *(float2*)(C + (size_t)row * ldc + col) = make_float2(v0 * on, v1 * on);
                } else if (mode == 4) {
                    unsigned short h0, l0, h1, l1;
                    split_bf16(v0, h0, l0);
                    split_bf16(v1, h1, l1);
                    *(ushort2*)(Ch + (size_t)row * ldc + col) = make_ushort2(h0, h1);
                    *(ushort2*)(Cl + (size_t)row * ldc + col) = make_ushort2(l0, l1);
                } else {
                    *(float2*)(C + (size_t)row * ldc + col) = make_float2(v0, v1);
                }
            }
        }
    }
}

// ---------------- pooling (gid sorted -> segments) ----------------
__global__ void k_gbound(const int* __restrict__ gid) {
    int i = blockIdx.x * blockDim.x + threadIdx.x;
    if (i >= Nn) return;
    if (i == 0) { for (int g = 0; g <= gid[0]; g++) g_start[g] = 0; }
    else if (gid[i] != gid[i - 1]) { for (int g = gid[i - 1] + 1; g <= gid[i]; g++) g_start[g] = i; }
    if (i == Nn - 1) { for (int g = gid[i] + 1; g <= Gg; g++) g_start[g] = Nn; }
}
__global__ void k_pool(const float* __restrict__ x) {
    int g = blockIdx.x, f = threadIdx.x;
    int s = g_start[g], e = g_start[g + 1];
    float acc = 0.f;
    for (int r = s; r < e; r++) acc += x[(size_t)r * Hh + f];
    float v = acc / fmaxf((float)(e - s), 1.f);
    unsigned short h, l;
    split_bf16(v, h, l);
    g_gsh[g * Hh + f] = h;
    g_gsl[g * Hh + f] = l;
}

__global__ void k_final(const float* __restrict__ z2, const float* __restrict__ W3,
                        const float* __restrict__ b3, float* __restrict__ out) {
    int gph = blockIdx.x;
    float acc = 0.f;
    for (int i = threadIdx.x; i < M2d; i += 128)
        acc += z2[gph * M2d + i] * W3[i];
#pragma unroll
    for (int off = 16; off; off >>= 1)
        acc += __shfl_down_sync(0xffffffffu, acc, off);
    __shared__ float sh[4];
    if ((threadIdx.x & 31) == 0) sh[threadIdx.x >> 5] = acc;
    __syncthreads();
    if (threadIdx.x == 0) out[gph] = sh[0] + sh[1] + sh[2] + sh[3] + b3[0];
}

// ---------------- host ----------------
extern "C" void kernel_launch(void* const* d_in, const int* in_sizes, int n_in,
                              void* d_out, int out_size) {
    const float* h    = (const float*)d_in[0];
    const int*   src  = (const int*)d_in[1];
    const int*   dst  = (const int*)d_in[2];
    const int*   gid  = (const int*)d_in[3];
    const float* W_in = (const float*)d_in[4];
    const float* b_in = (const float*)d_in[5];
    const float* Wg   = (const float*)d_in[6];
    const float* bg   = (const float*)d_in[7];
    const float* W1   = (const float*)d_in[8];
    const float* b1   = (const float*)d_in[9];
    const float* W2   = (const float*)d_in[10];
    const float* b2   = (const float*)d_in[11];
    const float* W3   = (const float*)d_in[12];
    const float* b3   = (const float*)d_in[13];
    float* out = (float*)d_out;

    float *p_x, *p_xs, *p_z2;
    int *p_rp, *p_cur, *p_part;
    unsigned short *p_mh, *p_ml, *p_gsh, *p_gsl, *p_z1h, *p_z1l;
    unsigned short *p_win_h, *p_win_l, *p_wg_h, *p_wg_l, *p_w1_h, *p_w1_l, *p_w2_h, *p_w2_l;
    cudaGetSymbolAddress((void**)&p_x,    g_x);
    cudaGetSymbolAddress((void**)&p_xs,   g_xs);
    cudaGetSymbolAddress((void**)&p_z2,   g_z2);
    cudaGetSymbolAddress((void**)&p_rp,   g_row_ptr);
    cudaGetSymbolAddress((void**)&p_cur,  g_cursor);
    cudaGetSymbolAddress((void**)&p_part, g_part);
    cudaGetSymbolAddress((void**)&p_mh,   g_mh);
    cudaGetSymbolAddress((void**)&p_ml,   g_ml);
    cudaGetSymbolAddress((void**)&p_gsh,  g_gsh);
    cudaGetSymbolAddress((void**)&p_gsl,  g_gsl);
    cudaGetSymbolAddress((void**)&p_z1h,  g_z1h);
    cudaGetSymbolAddress((void**)&p_z1l,  g_z1l);
    cudaGetSymbolAddress((void**)&p_win_h, g_WTin_hi);
    cudaGetSymbolAddress((void**)&p_win_l, g_WTin_lo);
    cudaGetSymbolAddress((void**)&p_wg_h,  g_WTg_hi);
    cudaGetSymbolAddress((void**)&p_wg_l,  g_WTg_lo);
    cudaGetSymbolAddress((void**)&p_w1_h,  g_WT1_hi);
    cudaGetSymbolAddress((void**)&p_w1_l,  g_WT1_lo);
    cudaGetSymbolAddress((void**)&p_w2_h,  g_WT2_hi);
    cudaGetSymbolAddress((void**)&p_w2_l,  g_WT2_lo);

    cudaFuncSetAttribute(k_bgemm, cudaFuncAttributeMaxDynamicSharedMemorySize, SMEM_SZ);

    const int TPB = 256, GB = 512;

    // ---- weight transpose + split ----
    k_wt<<<128, TPB>>>(W_in, Fin, Hh, 128, p_win_h, p_win_l);
    k_wt10<<<640, TPB>>>(Wg, p_wg_h, p_wg_l);
    k_wt<<<1024, TPB>>>(W1, Hh, M1d, Hh, p_w1_h, p_w1_l);
    k_wt<<<2048, TPB>>>(W2, M1d, M2d, M1d, p_w2_h, p_w2_l);

    // ---- CSR + norms ----
    k_zero_int<<<GB, TPB>>>(p_rp, Nn + 1);
    k_zero_int<<<GB, TPB>>>(p_cur, Nn);
    k_hist<<<GB, TPB>>>(src, dst);
    k_norms<<<GB, TPB>>>();
    int nscan = Nn + 1;
    int nb = (nscan + 1023) / 1024;
    k_scan1<<<nb, 1024>>>(p_rp, nscan, p_part);
    k_scan2<<<1, 32>>>(p_part, nb);
    k_scan3<<<nb, 1024>>>(p_rp, nscan, p_part);
    k_fill<<<GB, TPB>>>(src, dst);

    const int MT = (Nn + 127) / 128;     // 782
    const int SPB = (Nn + 7) / 8;        // 12500 blocks (8 warps = 8 rows each)

    // ---- input conv: scale -> spmm74 -> gemm (epilogue writes row-major xs) ----
    k_zero_int<<<GB, TPB>>>((int*)p_mh, Nn * 128 / 2);
    k_zero_int<<<GB, TPB>>>((int*)p_ml, Nn * 128 / 2);
    k_scale<<<GB, TPB>>>(h, p_xs, Nn * Fin, Fin);
    k_spmm74<<<Nn, 96>>>(p_xs, p_mh, p_ml);
    {
        dim3 grid(MT, Hh / 128);
        k_bgemm<<<grid, 256, SMEM_SZ>>>(p_mh, p_ml, Nn, 128, p_win_h, p_win_l,
                                        b_in, p_xs, 256, nullptr, nullptr, /*mode*/0);
    }

    // ---- 10 H x H graph convs ----
    for (int l = 0; l < 10; l++) {
        k_spmm256<<<SPB, 256>>>(p_xs, p_mh, p_ml);
        dim3 grid(MT, Hh / 128);
        int mode = (l < 9) ? 1 : 2;
        float* outp = (l < 9) ? p_xs : p_x;
        k_bgemm<<<grid, 256, SMEM_SZ>>>(p_mh, p_ml, Nn, 256,
                                        p_wg_h + (size_t)l * Hh * Hh, p_wg_l + (size_t)l * Hh * Hh,
                                        bg + (size_t)l * Hh,
                                        outp, 256, nullptr, nullptr, mode);
    }

    // ---- segment mean pooling -> split bf16 ----
    k_gbound<<<(Nn + TPB - 1) / TPB, TPB>>>(gid);
    k_pool<<<Gg, Hh>>>(p_x);

    // ---- MLP head ----
    {
        dim3 grid(Gg / 128, M1d / 128);
        k_bgemm<<<grid, 256, SMEM_SZ>>>(p_gsh, p_gsl, Gg, 256, p_w1_h, p_w1_l,
                                        b1, nullptr, M1d, p_z1h, p_z1l, /*mode*/4);
    }
    {
        dim3 grid(Gg / 128, M2d / 128);
        k_bgemm<<<grid, 256, SMEM_SZ>>>(p_z1h, p_z1l, Gg, 1024, p_w2_h, p_w2_l,
                                        b2, p_z2, M2d, nullptr, nullptr, /*mode*/3);
    }
    k_final<<<Gg, 128>>>(p_z2, W3, b3, out);
}